// round 11
// baseline (speedup 1.0000x reference)
#include <cuda_runtime.h>
#include <cuda_fp16.h>
#include <math.h>

#define BB 512
#define SS 336
#define FF 16
#define HH 256
#define PP 48
#define AK 272   // HH+FF

// ---------------- fragment-major prepared weights (device globals) ----------------
__device__ uint4 g_encWfrag[16*48*32];   // enc Whh  (393 KB)
__device__ uint4 g_encIfrag[   48*32];   // enc Wih  (24 KB, single ktile K=16)
__device__ uint4 g_decWfrag[32*48*32];   // dec [Whh | Wih] kt<16 / kt>=16 (786 KB)
__device__ uint4 g_attfrag [17*21*32];   // att_W 336x272 (183 KB)
__device__ __half g_eoutH[(size_t)BB*SS*HH]; // encoder outputs fp16 (88 MB)

__device__ __forceinline__ float sigf(float x) { return 1.f / (1.f + __expf(-x)); }
__device__ __forceinline__ unsigned int pk2(float a, float b) {
    __half2 h = __floats2half2_rn(a, b);
    return *reinterpret_cast<unsigned int*>(&h);
}

// ---------------- prep: build all fragments (unchanged layouts) ----------------
#define N_ENCW (16*48*32)
#define N_ENCI (48*32)
#define N_DECW (32*48*32)
#define N_ATT  (17*21*32)
#define PREP_N (N_ENCW + N_ENCI + N_DECW + N_ATT)

__global__ void k_prep(const float* __restrict__ eWih, const float* __restrict__ eWhh,
                       const float* __restrict__ dWih, const float* __restrict__ dWhh,
                       const float* __restrict__ attW)
{
    int idx = blockIdx.x * 256 + threadIdx.x;
    if (idx >= PREP_N) return;
    const float* src; uint4* dst; int mt, l, c0, ldk;
    if (idx < N_ENCW) {
        int kt = idx / 1536, r = idx % 1536; mt = r / 32; l = r % 32;
        c0 = kt*16 + (l & 3)*2; src = eWhh; ldk = HH; dst = &g_encWfrag[idx];
    } else if (idx < N_ENCW + N_ENCI) {
        int i = idx - N_ENCW; mt = i / 32; l = i % 32;
        c0 = (l & 3)*2; src = eWih; ldk = FF; dst = &g_encIfrag[i];
    } else if (idx < N_ENCW + N_ENCI + N_DECW) {
        int i = idx - N_ENCW - N_ENCI;
        int kt = i / 1536, r = i % 1536; mt = r / 32; l = r % 32;
        if (kt < 16) { src = dWhh; c0 = kt*16 + (l & 3)*2; }
        else         { src = dWih; c0 = (kt - 16)*16 + (l & 3)*2; }
        ldk = HH; dst = &g_decWfrag[i];
    } else {
        int i = idx - N_ENCW - N_ENCI - N_DECW;
        int kt = i / 672, r = i % 672; mt = r / 32; l = r % 32;
        c0 = kt*16 + (l & 3)*2; src = attW; ldk = AK; dst = &g_attfrag[i];
    }
    int mlo = mt*16 + (l >> 2), mhi = mlo + 8;
    uint4 o;
    o.x = pk2(src[mlo*ldk + c0],     src[mlo*ldk + c0 + 1]);
    o.y = pk2(src[mhi*ldk + c0],     src[mhi*ldk + c0 + 1]);
    o.z = pk2(src[mlo*ldk + c0 + 8], src[mlo*ldk + c0 + 9]);
    o.w = pk2(src[mhi*ldk + c0 + 8], src[mhi*ldk + c0 + 9]);
    *dst = o;
}

// ---------------- mma / cluster helpers ----------------
#define MMA(d, a, bb0, bb1) \
    asm volatile("mma.sync.aligned.m16n8k16.row.col.f32.f16.f16.f32 " \
        "{%0,%1,%2,%3}, {%4,%5,%6,%7}, {%8,%9}, {%0,%1,%2,%3};" \
        : "+f"(d[0]), "+f"(d[1]), "+f"(d[2]), "+f"(d[3]) \
        : "r"((a).x), "r"((a).y), "r"((a).z), "r"((a).w), "r"(bb0), "r"(bb1))

#define BFRAG(bb0, bb1, tb, RS, kbase) { \
    const __half* tp_ = (tb) + (l >> 2)*(RS) + (kbase) + (l & 3)*2; \
    bb0 = *(const unsigned int*)tp_; \
    bb1 = *(const unsigned int*)(tp_ + 8); }

__device__ __forceinline__ unsigned int smem_u32(const void* p) {
    unsigned int a;
    asm("{ .reg .u64 t; cvta.to.shared.u64 t, %1; cvt.u32.u64 %0, t; }" : "=r"(a) : "l"(p));
    return a;
}
__device__ __forceinline__ unsigned int mapa32(unsigned int a, unsigned int r) {
    unsigned int o; asm("mapa.shared::cluster.u32 %0, %1, %2;" : "=r"(o) : "r"(a), "r"(r)); return o;
}
__device__ __forceinline__ void stc16(unsigned int a, unsigned short v) {
    asm volatile("st.shared::cluster.u16 [%0], %1;" :: "r"(a), "h"(v));
}
__device__ __forceinline__ void stc32(unsigned int a, unsigned int v) {
    asm volatile("st.shared::cluster.u32 [%0], %1;" :: "r"(a), "r"(v));
}
#define CLUSTER_SYNC() do { \
    asm volatile("barrier.cluster.arrive.aligned;" ::: "memory"); \
    asm volatile("barrier.cluster.wait.aligned;"   ::: "memory"); } while (0)

// smem layout (bytes)
#define WC_SLOTS 14
#define OFF_WC 0                          // 14*24*32*16 = 172032
#define OFF_PL 172032                     // 6 planes x 1280 f32 = 30720 (scores overlay)
#define OFF_HF 202752                     // f32 own-j hold [128][10]: 5120
#define OFF_HT 207872                     // fp16 h tables, 2 bufs x 8x312: 9984
#define OFF_CT 217856                     // fp16 comb [8][280]: 4480
#define OFF_BI 222336                     // f32 own-j biases [4][128]: 2048
#define OFF_AB 224384                     // f32 attb [336]: 1344
#define SMEM_BYTES 225728
#define HT_RS 312
#define CT_RS 280

__global__ __launch_bounds__(512, 1) __cluster_dims__(2, 1, 1)
void k_all(
    const float* __restrict__ xb,
    const float* __restrict__ ebih, const float* __restrict__ ebhh,
    const float* __restrict__ attb,
    const float* __restrict__ dbih, const float* __restrict__ dbhh,
    const float* __restrict__ outW, const float* __restrict__ outb,
    const float* __restrict__ linW, const float* __restrict__ linb,
    float* __restrict__ dout)
{
    extern __shared__ char smx[];
    uint4*  wc   = (uint4*)(smx + OFF_WC);
    float*  PL   = (float*)(smx + OFF_PL);
    float*  hF   = (float*)(smx + OFF_HF);
    __half* hTb0 = (__half*)(smx + OFF_HT);
    __half* hTb1 = (__half*)(smx + OFF_HT + 4992);
    __half* cT   = (__half*)(smx + OFF_CT);
    float*  BI   = (float*)(smx + OFF_BI);
    float*  AB   = (float*)(smx + OFF_AB);

    int tx = threadIdx.x, l = tx & 31, w = tx >> 5;
    unsigned int rank; asm("mov.u32 %0, %%cluster_ctarank;" : "=r"(rank));
    int b0 = (blockIdx.x >> 1) * 8;
    int jbase = (int)rank << 7;
    bool hv = (w < 8);
    int m1 = w, m2 = 16 + w;
    int mtg1 = (m1 >> 3)*16 + (int)rank*8 + (m1 & 7);
    int mtg2 = 32 + (int)rank*8 + (m2 & 7);

    unsigned int peerHT0 = mapa32(smem_u32(hTb0), rank ^ 1u);
    unsigned int peerHT1 = mapa32(smem_u32(hTb1), rank ^ 1u);
    unsigned int peerCT  = mapa32(smem_u32(cT),  rank ^ 1u);

    // ---- init: encoder weight cache (kt 0..12 + x slot 13), biases, state ----
    for (int e = tx; e < WC_SLOTS*768; e += 512) {
        int slot = e / 768, m = (e % 768) >> 5, ll = e & 31;
        int mtg = (m >> 3)*16 + (int)rank*8 + (m & 7);
        if (slot < 13)       wc[e] = g_encWfrag[(slot*48 + mtg)*32 + ll];
        else if (slot == 13) wc[e] = g_encIfrag[mtg*32 + ll];
    }
    if (tx < 128) {
        BI[tx]       = ebih[jbase + tx]        + ebhh[jbase + tx];
        BI[128 + tx] = ebih[HH + jbase + tx]   + ebhh[HH + jbase + tx];
        BI[256 + tx] = ebih[2*HH + jbase + tx];
        BI[384 + tx] = ebhh[2*HH + jbase + tx];
    }
    for (int e = tx; e < 1280; e += 512) hF[e] = 0.f;
    for (int e = tx; e < 8*HT_RS; e += 512) hTb0[e] = __float2half(0.f);
    __syncthreads();
    if (tx < 128) { int b = tx >> 4, f = tx & 15;
        hTb0[b*HT_RS + 256 + f] = __float2half(xb[((b0 + b)*SS + 0)*FF + f]); }
    CLUSTER_SYNC();

    // ================= ENCODER =================
    // hoisted loop-invariant streamed A-frags (ktiles 13..15)
    uint4 s1a[3], s2a[3];
    #pragma unroll
    for (int i2 = 0; i2 < 3; ++i2) {
        s1a[i2] = g_encWfrag[((13 + i2)*48 + mtg1)*32 + l];
        if (hv) s2a[i2] = g_encWfrag[((13 + i2)*48 + mtg2)*32 + l];
    }
    for (int s = 0; s < SS; ++s) {
        const __half* hTc = (s & 1) ? hTb1 : hTb0;
        __half*       hTn = (s & 1) ? hTb0 : hTb1;
        unsigned int peerN = (s & 1) ? peerHT0 : peerHT1;

        float accA0[4] = {}, accA0x[4] = {}, accA1[4] = {}, accB0[4] = {}, accB1[4] = {};
        unsigned int bb0, bb1;
        #pragma unroll
        for (int kt = 0; kt < 13; ++kt) {
            BFRAG(bb0, bb1, hTc, HT_RS, kt*16);
            uint4 a = wc[(kt*24 + m1)*32 + l];
            if (kt & 1) { MMA(accA0x, a, bb0, bb1); } else { MMA(accA0, a, bb0, bb1); }
            if (hv) { uint4 a2 = wc[(kt*24 + m2)*32 + l]; MMA(accA1, a2, bb0, bb1); }
        }
        #pragma unroll
        for (int i2 = 0; i2 < 3; ++i2) {
            BFRAG(bb0, bb1, hTc, HT_RS, (13 + i2)*16);
            if (i2 & 1) { MMA(accA0x, s1a[i2], bb0, bb1); } else { MMA(accA0, s1a[i2], bb0, bb1); }
            if (hv) MMA(accA1, s2a[i2], bb0, bb1);
        }
        {   // x tile (k 256..271 of h-table)
            BFRAG(bb0, bb1, hTc, HT_RS, 256);
            uint4 a = wc[(13*24 + m1)*32 + l];  MMA(accB0, a, bb0, bb1);
            if (hv) { uint4 a2 = wc[(13*24 + m2)*32 + l]; MMA(accB1, a2, bb0, bb1); }
        }
        {   // epilogue to gate planes (plane stride 1280 f32, row stride 10)
            int jr = (m1 & 7)*16 + (l >> 2), cb = (l & 3)*2;
            int g = m1 >> 3;
            *(float2*)&PL[g*1280 + jr*10 + cb]     = make_float2(accA0[0]+accA0x[0]+accB0[0], accA0[1]+accA0x[1]+accB0[1]);
            *(float2*)&PL[g*1280 + (jr+8)*10 + cb] = make_float2(accA0[2]+accA0x[2]+accB0[2], accA0[3]+accA0x[3]+accB0[3]);
            if (hv) {
                int jr2 = (m2 & 7)*16 + (l >> 2);
                *(float2*)&PL[2*1280 + jr2*10 + cb]     = make_float2(accA1[0], accA1[1]);
                *(float2*)&PL[2*1280 + (jr2+8)*10 + cb] = make_float2(accA1[2], accA1[3]);
                *(float2*)&PL[3*1280 + jr2*10 + cb]     = make_float2(accB1[0], accB1[1]);
                *(float2*)&PL[3*1280 + (jr2+8)*10 + cb] = make_float2(accB1[2], accB1[3]);
            }
        }
        __syncthreads();
        {   // GRU update: own 128 j's; push h2 to both h-tables
            int jl = tx & 127, j = jbase + jl, pr = tx >> 7;
            #pragma unroll
            for (int q = 0; q < 2; ++q) {
                int b = pr*2 + q;
                float r = sigf(PL[jl*10 + b] + BI[jl]);
                float z = sigf(PL[1280 + jl*10 + b] + BI[128 + jl]);
                float n = tanhf(PL[3*1280 + jl*10 + b] + BI[256 + jl]
                              + r*(PL[2*1280 + jl*10 + b] + BI[384 + jl]));
                float hold = hF[jl*10 + b];
                float h2 = (1.f - z)*n + z*hold;
                hF[jl*10 + b] = h2;
                __half hh = __float2half(h2);
                hTn[b*HT_RS + j] = hh;
                stc16(peerN + (unsigned)(b*HT_RS + j)*2, *(unsigned short*)&hh);
                g_eoutH[((size_t)(b0 + b)*SS + s)*HH + j] = hh;
            }
            if (tx < 128 && s + 1 < SS) { int b = tx >> 4, f = tx & 15;
                hTn[b*HT_RS + 256 + f] = __float2half(xb[((b0 + b)*SS + s + 1)*FF + f]); }
        }
        CLUSTER_SYNC();
    }

    // ================= DECODER setup =================
    for (int e = tx; e < WC_SLOTS*768; e += 512) {
        int slot = e / 768, m = (e % 768) >> 5, ll = e & 31;
        int mtg = (m >> 3)*16 + (int)rank*8 + (m & 7);
        wc[e] = g_decWfrag[(slot*48 + mtg)*32 + ll];
    }
    if (tx < 128) {
        BI[tx]       = dbih[jbase + tx]        + dbhh[jbase + tx];
        BI[128 + tx] = dbih[HH + jbase + tx]   + dbhh[HH + jbase + tx];
        BI[256 + tx] = dbih[2*HH + jbase + tx];
        BI[384 + tx] = dbhh[2*HH + jbase + tx];
    }
    for (int e = tx; e < SS; e += 512) AB[e] = attb[e];
    if (tx < 128) { int b = tx >> 4, f = tx & 15;
        hTb0[b*HT_RS + 256 + f] = __float2half(xb[((b0 + b)*SS + (SS - 1))*FF + f]); }
    __syncthreads();

    for (int p = 0; p < PP; ++p) {
        const __half* hTc = (p & 1) ? hTb1 : hTb0;
        __half*       hTn = (p & 1) ? hTb0 : hTb1;
        unsigned int peerN = (p & 1) ? peerHT0 : peerHT1;

        // ---- A: attention scores (both ranks compute all 336) ----
        {
            float ac0[4] = {}, ac0x[4] = {}, ac1[4] = {};
            unsigned int bb0, bb1;
            bool two = (w < 5);
            uint4 p1 = g_attfrag[(0*21 + w)*32 + l], p2 = p1;
            if (two) p2 = g_attfrag[(0*21 + 16 + w)*32 + l];
            #pragma unroll 1
            for (int kt = 0; kt < 17; ++kt) {
                uint4 c1 = p1, c2 = p2;
                if (kt < 16) {
                    p1 = g_attfrag[((kt + 1)*21 + w)*32 + l];
                    if (two) p2 = g_attfrag[((kt + 1)*21 + 16 + w)*32 + l];
                }
                BFRAG(bb0, bb1, hTc, HT_RS, kt*16);
                if (kt & 1) { MMA(ac0x, c1, bb0, bb1); } else { MMA(ac0, c1, bb0, bb1); }
                if (two) MMA(ac1, c2, bb0, bb1);
            }
            int cb = (l & 3)*2, ro = l >> 2;
            int sr = w*16 + ro;
            *(float2*)&PL[sr*8 + cb]       = make_float2(ac0[0]+ac0x[0] + AB[sr],     ac0[1]+ac0x[1] + AB[sr]);
            *(float2*)&PL[(sr + 8)*8 + cb] = make_float2(ac0[2]+ac0x[2] + AB[sr + 8], ac0[3]+ac0x[3] + AB[sr + 8]);
            if (two) {
                int sr2 = (16 + w)*16 + ro;
                *(float2*)&PL[sr2*8 + cb]       = make_float2(ac1[0] + AB[sr2],     ac1[1] + AB[sr2]);
                *(float2*)&PL[(sr2 + 8)*8 + cb] = make_float2(ac1[2] + AB[sr2 + 8], ac1[3] + AB[sr2 + 8]);
            }
        }
        __syncthreads();
        // ---- B: softmax (warp = batch row) ----
        if (w < 8) {
            float mx = -1e30f;
            for (int i = l; i < SS; i += 32) mx = fmaxf(mx, PL[i*8 + w]);
            #pragma unroll
            for (int o = 16; o; o >>= 1) mx = fmaxf(mx, __shfl_xor_sync(0xffffffffu, mx, o));
            float sum = 0.f;
            for (int i = l; i < SS; i += 32) {
                float e = __expf(PL[i*8 + w] - mx);
                PL[i*8 + w] = e; sum += e;
            }
            #pragma unroll
            for (int o = 16; o; o >>= 1) sum += __shfl_xor_sync(0xffffffffu, sum, o);
            float inv = 1.f / sum;
            for (int i = l; i < SS; i += 32) PL[i*8 + w] *= inv;
        }
        __syncthreads();
        // ---- C || D1: warps 0-7 combine (L2-bound) while warps 8-15 do Whh x h mma ----
        float accA[3][4] = {};
        if (w < 8) {
            int b = w;
            const uint2* ep = (const uint2*)(g_eoutH + (size_t)(b0 + b)*SS*HH) + (int)rank*32 + l;
            float c0 = 0, c1 = 0, c2 = 0, c3 = 0;
            #pragma unroll 4
            for (int s2 = 0; s2 < SS; ++s2) {
                float a = PL[s2*8 + b];
                uint2 u = ep[(size_t)s2*64];
                float2 f01 = __half22float2(*(__half2*)&u.x);
                float2 f23 = __half22float2(*(__half2*)&u.y);
                c0 += a*f01.x; c1 += a*f01.y; c2 += a*f23.x; c3 += a*f23.y;
            }
            __half2 lo = __floats2half2_rn(c0, c1), hi = __floats2half2_rn(c2, c3);
            int col = jbase + l*4;
            *(__half2*)&cT[b*CT_RS + col]     = lo;
            *(__half2*)&cT[b*CT_RS + col + 2] = hi;
            unsigned int ad = peerCT + (unsigned)(b*CT_RS + col)*2;
            stc32(ad,     *(unsigned int*)&lo);
            stc32(ad + 4, *(unsigned int*)&hi);
        } else {
            int mtgA[3];
            #pragma unroll
            for (int i = 0; i < 3; ++i) {
                int m = (w - 8)*3 + i;
                mtgA[i] = (m >> 3)*16 + (int)rank*8 + (m & 7);
            }
            uint4 st14[3], st15[3];
            #pragma unroll
            for (int i = 0; i < 3; ++i) {
                st14[i] = g_decWfrag[(14*48 + mtgA[i])*32 + l];
                st15[i] = g_decWfrag[(15*48 + mtgA[i])*32 + l];
            }
            unsigned int bb0, bb1;
            #pragma unroll
            for (int kt = 0; kt < 14; ++kt) {
                BFRAG(bb0, bb1, hTc, HT_RS, kt*16);
                #pragma unroll
                for (int i = 0; i < 3; ++i) {
                    uint4 a = wc[(kt*24 + (w - 8)*3 + i)*32 + l];
                    MMA(accA[i], a, bb0, bb1);
                }
            }
            BFRAG(bb0, bb1, hTc, HT_RS, 14*16);
            #pragma unroll
            for (int i = 0; i < 3; ++i) MMA(accA[i], st14[i], bb0, bb1);
            BFRAG(bb0, bb1, hTc, HT_RS, 15*16);
            #pragma unroll
            for (int i = 0; i < 3; ++i) MMA(accA[i], st15[i], bb0, bb1);
        }
        CLUSTER_SYNC();
        // ---- D2: Wih x comb (kt 16..31, all warps) + epilogue to 6 planes ----
        {
            float accB0[4] = {}, accB0x[4] = {}, accB1[4] = {};
            unsigned int bb0, bb1;
            uint4 p1 = g_decWfrag[(16*48 + mtg1)*32 + l], p2 = p1;
            if (hv) p2 = g_decWfrag[(16*48 + mtg2)*32 + l];
            #pragma unroll 1
            for (int kt = 16; kt < 32; ++kt) {
                uint4 c1 = p1, c2 = p2;
                if (kt < 31) {
                    p1 = g_decWfrag[((kt + 1)*48 + mtg1)*32 + l];
                    if (hv) p2 = g_decWfrag[((kt + 1)*48 + mtg2)*32 + l];
                }
                BFRAG(bb0, bb1, cT, CT_RS, (kt - 16)*16);
                if (kt & 1) { MMA(accB0x, c1, bb0, bb1); } else { MMA(accB0, c1, bb0, bb1); }
                if (hv) MMA(accB1, c2, bb0, bb1);
            }
            int jr = (m1 & 7)*16 + (l >> 2), cb = (l & 3)*2;
            int g = m1 >> 3;   // 0=r, 1=z
            *(float2*)&PL[(3 + g)*1280 + jr*10 + cb]     = make_float2(accB0[0]+accB0x[0], accB0[1]+accB0x[1]);
            *(float2*)&PL[(3 + g)*1280 + (jr+8)*10 + cb] = make_float2(accB0[2]+accB0x[2], accB0[3]+accB0x[3]);
            if (hv) {
                int jr2 = (m2 & 7)*16 + (l >> 2);
                *(float2*)&PL[5*1280 + jr2*10 + cb]     = make_float2(accB1[0], accB1[1]);
                *(float2*)&PL[5*1280 + (jr2+8)*10 + cb] = make_float2(accB1[2], accB1[3]);
            }
            if (w >= 8) {
                #pragma unroll
                for (int i = 0; i < 3; ++i) {
                    int m = (w - 8)*3 + i;
                    int ga = m >> 3;    // 0=Ar, 1=Az, 2=Anh
                    int jrA = (m & 7)*16 + (l >> 2);
                    *(float2*)&PL[ga*1280 + jrA*10 + cb]     = make_float2(accA[i][0], accA[i][1]);
                    *(float2*)&PL[ga*1280 + (jrA+8)*10 + cb] = make_float2(accA[i][2], accA[i][3]);
                }
            }
        }
        __syncthreads();
        {   // GRU update own j's; push h2 to both h-tables
            int jl = tx & 127, j = jbase + jl, pr = tx >> 7;
            #pragma unroll
            for (int q = 0; q < 2; ++q) {
                int b = pr*2 + q;
                float r = sigf(PL[jl*10 + b] + PL[3*1280 + jl*10 + b] + BI[jl]);
                float z = sigf(PL[1280 + jl*10 + b] + PL[4*1280 + jl*10 + b] + BI[128 + jl]);
                float n = tanhf(PL[5*1280 + jl*10 + b] + BI[256 + jl]
                              + r*(PL[2*1280 + jl*10 + b] + BI[384 + jl]));
                float hold = hF[jl*10 + b];
                float h2 = (1.f - z)*n + z*hold;
                hF[jl*10 + b] = h2;
                __half hh = __float2half(h2);
                hTn[b*HT_RS + j] = hh;
                stc16(peerN + (unsigned)(b*HT_RS + j)*2, *(unsigned short*)&hh);
            }
        }
        CLUSTER_SYNC();
        // ---- E: out projection + final linear (both ranks; rank0 writes dout) ----
        if (w < 8) {
            float fin = 0.f;
            #pragma unroll
            for (int f = 0; f < FF; ++f) {
                float acc = 0.f;
                #pragma unroll
                for (int k = l; k < HH; k += 32)
                    acc += __half2float(hTn[w*HT_RS + k]) * outW[f*HH + k];
                #pragma unroll
                for (int o = 16; o; o >>= 1) acc += __shfl_xor_sync(0xffffffffu, acc, o);
                if (l == 0) {
                    float ov = acc + outb[f];
                    hTn[w*HT_RS + 256 + f] = __float2half(ov);
                    fin += ov * linW[f];
                }
            }
            if (l == 0 && rank == 0) dout[(b0 + w)*PP + p] = fin + linb[0];
        }
        __syncthreads();
    }
}

// ---------------- launch ----------------
extern "C" void kernel_launch(void* const* d_in, const int* in_sizes, int n_in,
                              void* d_out, int out_size)
{
    const float* xb   = (const float*)d_in[0];
    const float* eWih = (const float*)d_in[1];
    const float* eWhh = (const float*)d_in[2];
    const float* ebih = (const float*)d_in[3];
    const float* ebhh = (const float*)d_in[4];
    const float* attW = (const float*)d_in[5];
    const float* attb = (const float*)d_in[6];
    const float* dWih = (const float*)d_in[7];
    const float* dWhh = (const float*)d_in[8];
    const float* dbih = (const float*)d_in[9];
    const float* dbhh = (const float*)d_in[10];
    const float* outW = (const float*)d_in[11];
    const float* outb = (const float*)d_in[12];
    const float* linW = (const float*)d_in[13];
    const float* linb = (const float*)d_in[14];
    float* dout = (float*)d_out;

    cudaFuncSetAttribute(k_all, cudaFuncAttributeMaxDynamicSharedMemorySize, SMEM_BYTES);

    k_prep<<<(PREP_N + 255) / 256, 256>>>(eWih, eWhh, dWih, dWhh, attW);
    k_all<<<BB / 4, 512, SMEM_BYTES>>>(xb, ebih, ebhh, attb, dbih, dbhh,
                                       outW, outb, linW, linb, dout);
}

// round 12
// speedup vs baseline: 1.1340x; 1.1340x over previous
#include <cuda_runtime.h>
#include <cuda_fp16.h>
#include <math.h>

#define BB 512
#define SS 336
#define FF 16
#define HH 256
#define PP 48
#define AK 272   // HH+FF

// ---------------- fragment-major prepared weights (device globals) ----------------
__device__ uint4 g_encWfrag[16*48*32];   // enc Whh  (393 KB)
__device__ uint4 g_encIfrag[   48*32];   // enc Wih  (24 KB, single ktile K=16)
__device__ uint4 g_decWfrag[32*48*32];   // dec [Whh | Wih] kt<16 / kt>=16 (786 KB)
__device__ uint4 g_attfrag [17*21*32];   // att_W 336x272 (183 KB)
__device__ __half g_eoutH[(size_t)BB*SS*HH]; // encoder outputs fp16 (88 MB)

__device__ __forceinline__ float sigf(float x) { return 1.f / (1.f + __expf(-x)); }
__device__ __forceinline__ unsigned int pk2(float a, float b) {
    __half2 h = __floats2half2_rn(a, b);
    return *reinterpret_cast<unsigned int*>(&h);
}

// ---------------- prep: build all fragments (unchanged layouts) ----------------
#define N_ENCW (16*48*32)
#define N_ENCI (48*32)
#define N_DECW (32*48*32)
#define N_ATT  (17*21*32)
#define PREP_N (N_ENCW + N_ENCI + N_DECW + N_ATT)

__global__ void k_prep(const float* __restrict__ eWih, const float* __restrict__ eWhh,
                       const float* __restrict__ dWih, const float* __restrict__ dWhh,
                       const float* __restrict__ attW)
{
    int idx = blockIdx.x * 256 + threadIdx.x;
    if (idx >= PREP_N) return;
    const float* src; uint4* dst; int mt, l, c0, ldk;
    if (idx < N_ENCW) {
        int kt = idx / 1536, r = idx % 1536; mt = r / 32; l = r % 32;
        c0 = kt*16 + (l & 3)*2; src = eWhh; ldk = HH; dst = &g_encWfrag[idx];
    } else if (idx < N_ENCW + N_ENCI) {
        int i = idx - N_ENCW; mt = i / 32; l = i % 32;
        c0 = (l & 3)*2; src = eWih; ldk = FF; dst = &g_encIfrag[i];
    } else if (idx < N_ENCW + N_ENCI + N_DECW) {
        int i = idx - N_ENCW - N_ENCI;
        int kt = i / 1536, r = i % 1536; mt = r / 32; l = r % 32;
        if (kt < 16) { src = dWhh; c0 = kt*16 + (l & 3)*2; }
        else         { src = dWih; c0 = (kt - 16)*16 + (l & 3)*2; }
        ldk = HH; dst = &g_decWfrag[i];
    } else {
        int i = idx - N_ENCW - N_ENCI - N_DECW;
        int kt = i / 672, r = i % 672; mt = r / 32; l = r % 32;
        c0 = kt*16 + (l & 3)*2; src = attW; ldk = AK; dst = &g_attfrag[i];
    }
    int mlo = mt*16 + (l >> 2), mhi = mlo + 8;
    uint4 o;
    o.x = pk2(src[mlo*ldk + c0],     src[mlo*ldk + c0 + 1]);
    o.y = pk2(src[mhi*ldk + c0],     src[mhi*ldk + c0 + 1]);
    o.z = pk2(src[mlo*ldk + c0 + 8], src[mlo*ldk + c0 + 9]);
    o.w = pk2(src[mhi*ldk + c0 + 8], src[mhi*ldk + c0 + 9]);
    *dst = o;
}

// ---------------- mma / cluster helpers ----------------
#define MMA(d, a, bb0, bb1) \
    asm volatile("mma.sync.aligned.m16n8k16.row.col.f32.f16.f16.f32 " \
        "{%0,%1,%2,%3}, {%4,%5,%6,%7}, {%8,%9}, {%0,%1,%2,%3};" \
        : "+f"(d[0]), "+f"(d[1]), "+f"(d[2]), "+f"(d[3]) \
        : "r"((a).x), "r"((a).y), "r"((a).z), "r"((a).w), "r"(bb0), "r"(bb1))

#define BFRAG(bb0, bb1, tb, RS, kbase) { \
    const __half* tp_ = (tb) + (l >> 2)*(RS) + (kbase) + (l & 3)*2; \
    bb0 = *(const unsigned int*)tp_; \
    bb1 = *(const unsigned int*)(tp_ + 8); }

__device__ __forceinline__ unsigned int smem_u32(const void* p) {
    unsigned int a;
    asm("{ .reg .u64 t; cvta.to.shared.u64 t, %1; cvt.u32.u64 %0, t; }" : "=r"(a) : "l"(p));
    return a;
}
__device__ __forceinline__ unsigned int mapa32(unsigned int a, unsigned int r) {
    unsigned int o; asm("mapa.shared::cluster.u32 %0, %1, %2;" : "=r"(o) : "r"(a), "r"(r)); return o;
}
__device__ __forceinline__ void stc16(unsigned int a, unsigned short v) {
    asm volatile("st.shared::cluster.u16 [%0], %1;" :: "r"(a), "h"(v));
}
__device__ __forceinline__ void stc32(unsigned int a, unsigned int v) {
    asm volatile("st.shared::cluster.u32 [%0], %1;" :: "r"(a), "r"(v));
}
#define CLUSTER_SYNC() do { \
    asm volatile("barrier.cluster.arrive.aligned;" ::: "memory"); \
    asm volatile("barrier.cluster.wait.aligned;"   ::: "memory"); } while (0)

// smem layout (bytes)
#define WC_SLOTS 14
#define OFF_WC 0                          // 14*24*32*16 = 172032
#define OFF_PL 172032                     // 6 planes x 1280 f32 = 30720 (scores/SCR overlay)
#define OFF_HF 202752                     // f32 own-j hold [128][10]: 5120
#define OFF_HT 207872                     // fp16 h tables, 2 bufs x 8x312: 9984
#define OFF_CT 217856                     // fp16 comb [8][280]: 4480
#define OFF_BI 222336                     // f32 own-j biases [4][128]: 2048
#define OFF_AB 224384                     // f32 attb [336]: 1344
#define SMEM_BYTES 225728
#define HT_RS 312
#define CT_RS 280

__global__ __launch_bounds__(512, 1) __cluster_dims__(2, 1, 1)
void k_all(
    const float* __restrict__ xb,
    const float* __restrict__ ebih, const float* __restrict__ ebhh,
    const float* __restrict__ attb,
    const float* __restrict__ dbih, const float* __restrict__ dbhh,
    const float* __restrict__ outW, const float* __restrict__ outb,
    const float* __restrict__ linW, const float* __restrict__ linb,
    float* __restrict__ dout)
{
    extern __shared__ char smx[];
    uint4*  wc   = (uint4*)(smx + OFF_WC);
    float*  PL   = (float*)(smx + OFF_PL);
    float*  SCR  = (float*)(smx + OFF_PL + 12288);
    float*  hF   = (float*)(smx + OFF_HF);
    __half* hTb0 = (__half*)(smx + OFF_HT);
    __half* hTb1 = (__half*)(smx + OFF_HT + 4992);
    __half* cT   = (__half*)(smx + OFF_CT);
    float*  BI   = (float*)(smx + OFF_BI);
    float*  AB   = (float*)(smx + OFF_AB);

    int tx = threadIdx.x, l = tx & 31, w = tx >> 5;
    unsigned int rank; asm("mov.u32 %0, %%cluster_ctarank;" : "=r"(rank));
    int b0 = (blockIdx.x >> 1) * 8;
    int jbase = (int)rank << 7;
    int m1 = w;
    int m2loc = 16 + (w & 7);
    int mtg1 = (m1 >> 3)*16 + (int)rank*8 + (m1 & 7);
    int mtg2 = 32 + (int)rank*8 + (w & 7);
    bool hiW = (w >= 8);

    unsigned int peerHT0 = mapa32(smem_u32(hTb0), rank ^ 1u);
    unsigned int peerHT1 = mapa32(smem_u32(hTb1), rank ^ 1u);
    unsigned int peerCT  = mapa32(smem_u32(cT),  rank ^ 1u);

    // ---- init: encoder weight cache (kt 0..12 + x slot 13), biases, state ----
    for (int e = tx; e < WC_SLOTS*768; e += 512) {
        int slot = e / 768, m = (e % 768) >> 5, ll = e & 31;
        int mtg = (m >> 3)*16 + (int)rank*8 + (m & 7);
        if (slot < 13)       wc[e] = g_encWfrag[(slot*48 + mtg)*32 + ll];
        else if (slot == 13) wc[e] = g_encIfrag[mtg*32 + ll];
    }
    if (tx < 128) {
        BI[tx]       = ebih[jbase + tx]        + ebhh[jbase + tx];
        BI[128 + tx] = ebih[HH + jbase + tx]   + ebhh[HH + jbase + tx];
        BI[256 + tx] = ebih[2*HH + jbase + tx];
        BI[384 + tx] = ebhh[2*HH + jbase + tx];
    }
    for (int e = tx; e < 1280; e += 512) hF[e] = 0.f;
    for (int e = tx; e < 8*HT_RS; e += 512) hTb0[e] = __float2half(0.f);
    __syncthreads();
    if (tx < 128) { int b = tx >> 4, f = tx & 15;
        hTb0[b*HT_RS + 256 + f] = __float2half(xb[((b0 + b)*SS + 0)*FF + f]); }
    CLUSTER_SYNC();

    // ================= ENCODER =================
    // m1 = own r/z tile (all 16-17 ktiles); m2 (gate-n tile) k-split across warp pair (w, w+8)
    for (int s = 0; s < SS; ++s) {
        const __half* hTc = (s & 1) ? hTb1 : hTb0;
        __half*       hTn = (s & 1) ? hTb0 : hTb1;
        unsigned int peerN = (s & 1) ? peerHT0 : peerHT1;

        float accA0[4] = {}, accA0x[4] = {}, accB0[4] = {}, accN[4] = {}, accNx[4] = {};
        unsigned int bb0, bb1;
        #pragma unroll
        for (int kt = 0; kt < 13; ++kt) {
            BFRAG(bb0, bb1, hTc, HT_RS, kt*16);
            uint4 a = wc[(kt*24 + m1)*32 + l];
            if (kt & 1) { MMA(accA0x, a, bb0, bb1); } else { MMA(accA0, a, bb0, bb1); }
            bool mine = hiW ? (kt >= 8) : (kt < 8);
            if (mine) { uint4 a2 = wc[(kt*24 + m2loc)*32 + l]; MMA(accN, a2, bb0, bb1); }
        }
        #pragma unroll
        for (int i2 = 0; i2 < 3; ++i2) {      // streamed ktiles 13..15
            uint4 s1 = g_encWfrag[((13 + i2)*48 + mtg1)*32 + l];
            BFRAG(bb0, bb1, hTc, HT_RS, (13 + i2)*16);
            if (i2 & 1) { MMA(accA0x, s1, bb0, bb1); } else { MMA(accA0, s1, bb0, bb1); }
            if (hiW) { uint4 s2 = g_encWfrag[((13 + i2)*48 + mtg2)*32 + l]; MMA(accN, s2, bb0, bb1); }
        }
        {   // x tile (k 256..271 of h-table)
            BFRAG(bb0, bb1, hTc, HT_RS, 256);
            uint4 a = wc[(13*24 + m1)*32 + l];  MMA(accB0, a, bb0, bb1);
            if (hiW) { uint4 a2 = wc[(13*24 + m2loc)*32 + l]; MMA(accNx, a2, bb0, bb1); }
        }
        {   // epilogue: plane stride 1280 f32, row stride 10
            int jr = (m1 & 7)*16 + (l >> 2), cb = (l & 3)*2;
            int g = m1 >> 3;
            *(float2*)&PL[g*1280 + jr*10 + cb]     = make_float2(accA0[0]+accA0x[0]+accB0[0], accA0[1]+accA0x[1]+accB0[1]);
            *(float2*)&PL[g*1280 + (jr+8)*10 + cb] = make_float2(accA0[2]+accA0x[2]+accB0[2], accA0[3]+accA0x[3]+accB0[3]);
            int jr2 = (w & 7)*16 + (l >> 2);
            if (!hiW) {
                *(float2*)&PL[2*1280 + jr2*10 + cb]     = make_float2(accN[0], accN[1]);
                *(float2*)&PL[2*1280 + (jr2+8)*10 + cb] = make_float2(accN[2], accN[3]);
            } else {
                *(float2*)&PL[4*1280 + jr2*10 + cb]     = make_float2(accN[0], accN[1]);
                *(float2*)&PL[4*1280 + (jr2+8)*10 + cb] = make_float2(accN[2], accN[3]);
                *(float2*)&PL[3*1280 + jr2*10 + cb]     = make_float2(accNx[0], accNx[1]);
                *(float2*)&PL[3*1280 + (jr2+8)*10 + cb] = make_float2(accNx[2], accNx[3]);
            }
        }
        __syncthreads();
        {   // GRU update: own 128 j's; push h2 to both h-tables
            int jl = tx & 127, j = jbase + jl, pr = tx >> 7;
            #pragma unroll
            for (int q = 0; q < 2; ++q) {
                int b = pr*2 + q;
                float r = sigf(PL[jl*10 + b] + BI[jl]);
                float z = sigf(PL[1280 + jl*10 + b] + BI[128 + jl]);
                float nh = PL[2*1280 + jl*10 + b] + PL[4*1280 + jl*10 + b] + BI[384 + jl];
                float nx = PL[3*1280 + jl*10 + b] + BI[256 + jl];
                float n = tanhf(nx + r*nh);
                float hold = hF[jl*10 + b];
                float h2 = (1.f - z)*n + z*hold;
                hF[jl*10 + b] = h2;
                __half hh = __float2half(h2);
                hTn[b*HT_RS + j] = hh;
                stc16(peerN + (unsigned)(b*HT_RS + j)*2, *(unsigned short*)&hh);
                g_eoutH[((size_t)(b0 + b)*SS + s)*HH + j] = hh;
            }
            if (tx < 128 && s + 1 < SS) { int b = tx >> 4, f = tx & 15;
                hTn[b*HT_RS + 256 + f] = __float2half(xb[((b0 + b)*SS + s + 1)*FF + f]); }
        }
        CLUSTER_SYNC();
    }

    // ================= DECODER setup =================
    for (int e = tx; e < WC_SLOTS*768; e += 512) {
        int slot = e / 768, m = (e % 768) >> 5, ll = e & 31;
        int mtg = (m >> 3)*16 + (int)rank*8 + (m & 7);
        wc[e] = g_decWfrag[(slot*48 + mtg)*32 + ll];
    }
    if (tx < 128) {
        BI[tx]       = dbih[jbase + tx]        + dbhh[jbase + tx];
        BI[128 + tx] = dbih[HH + jbase + tx]   + dbhh[HH + jbase + tx];
        BI[256 + tx] = dbih[2*HH + jbase + tx];
        BI[384 + tx] = dbhh[2*HH + jbase + tx];
    }
    for (int e = tx; e < SS; e += 512) AB[e] = attb[e];
    if (tx < 128) { int b = tx >> 4, f = tx & 15;
        hTb0[b*HT_RS + 256 + f] = __float2half(xb[((b0 + b)*SS + (SS - 1))*FF + f]); }
    __syncthreads();

    for (int p = 0; p < PP; ++p) {
        const __half* hTc = (p & 1) ? hTb1 : hTb0;
        __half*       hTn = (p & 1) ? hTb0 : hTb1;
        unsigned int peerN = (p & 1) ? peerHT0 : peerHT1;

        // ---- A: attention scores (both ranks compute all 336) ----
        {
            float ac0[4] = {}, ac1[4] = {};
            unsigned int bb0, bb1;
            bool two = (w < 5);
            uint4 p1 = g_attfrag[(0*21 + w)*32 + l], p2 = p1;
            if (two) p2 = g_attfrag[(0*21 + 16 + w)*32 + l];
            #pragma unroll 1
            for (int kt = 0; kt < 17; ++kt) {
                uint4 c1 = p1, c2 = p2;
                if (kt < 16) {
                    p1 = g_attfrag[((kt + 1)*21 + w)*32 + l];
                    if (two) p2 = g_attfrag[((kt + 1)*21 + 16 + w)*32 + l];
                }
                BFRAG(bb0, bb1, hTc, HT_RS, kt*16);
                MMA(ac0, c1, bb0, bb1);
                if (two) MMA(ac1, c2, bb0, bb1);
            }
            int cb = (l & 3)*2, ro = l >> 2;
            int sr = w*16 + ro;
            *(float2*)&PL[sr*8 + cb]       = make_float2(ac0[0] + AB[sr],     ac0[1] + AB[sr]);
            *(float2*)&PL[(sr + 8)*8 + cb] = make_float2(ac0[2] + AB[sr + 8], ac0[3] + AB[sr + 8]);
            if (two) {
                int sr2 = (16 + w)*16 + ro;
                *(float2*)&PL[sr2*8 + cb]       = make_float2(ac1[0] + AB[sr2],     ac1[1] + AB[sr2]);
                *(float2*)&PL[(sr2 + 8)*8 + cb] = make_float2(ac1[2] + AB[sr2 + 8], ac1[3] + AB[sr2 + 8]);
            }
        }
        __syncthreads();
        // ---- B: softmax (warp = batch row) ----
        if (w < 8) {
            float mx = -1e30f;
            for (int i = l; i < SS; i += 32) mx = fmaxf(mx, PL[i*8 + w]);
            #pragma unroll
            for (int o = 16; o; o >>= 1) mx = fmaxf(mx, __shfl_xor_sync(0xffffffffu, mx, o));
            float sum = 0.f;
            for (int i = l; i < SS; i += 32) {
                float e = __expf(PL[i*8 + w] - mx);
                PL[i*8 + w] = e; sum += e;
            }
            #pragma unroll
            for (int o = 16; o; o >>= 1) sum += __shfl_xor_sync(0xffffffffu, sum, o);
            float inv = 1.f / sum;
            for (int i = l; i < SS; i += 32) PL[i*8 + w] *= inv;
        }
        __syncthreads();
        // ---- C: combine own 128 h-cols; write cT to both ranks (16 warps) ----
        {
            int b = tx >> 6, t = tx & 63, shalf = t >> 5, cq = t & 31;
            const uint2* ep = (const uint2*)(g_eoutH + (size_t)(b0 + b)*SS*HH) + (int)rank*32 + cq;
            float c0 = 0, c1 = 0, c2 = 0, c3 = 0;
            int s0 = shalf*168;
            #pragma unroll 4
            for (int s2 = s0; s2 < s0 + 168; ++s2) {
                float a = PL[s2*8 + b];
                uint2 u = ep[(size_t)s2*64];
                float2 f01 = __half22float2(*(__half2*)&u.x);
                float2 f23 = __half22float2(*(__half2*)&u.y);
                c0 += a*f01.x; c1 += a*f01.y; c2 += a*f23.x; c3 += a*f23.y;
            }
            if (shalf) *(float4*)&SCR[(b*32 + cq)*4] = make_float4(c0, c1, c2, c3);
            __syncthreads();
            if (!shalf) {
                float4 pv = *(float4*)&SCR[(b*32 + cq)*4];
                c0 += pv.x; c1 += pv.y; c2 += pv.z; c3 += pv.w;
                __half2 lo = __floats2half2_rn(c0, c1), hi = __floats2half2_rn(c2, c3);
                int col = jbase + cq*4;
                *(__half2*)&cT[b*CT_RS + col]     = lo;
                *(__half2*)&cT[b*CT_RS + col + 2] = hi;
                unsigned int ad = peerCT + (unsigned)(b*CT_RS + col)*2;
                stc32(ad,     *(unsigned int*)&lo);
                stc32(ad + 4, *(unsigned int*)&hi);
            }
        }
        CLUSTER_SYNC();
        // ---- D: decoder GRU mma, balanced 48/48 (m1 full; m2 k-split across warp pair) ----
        {
            float accH[4] = {}, accHx[4] = {}, accC[4] = {}, accCx[4] = {};
            float accNh[4] = {}, accNx[4] = {};
            unsigned int bb0, bb1;
            #pragma unroll
            for (int kt = 0; kt < 14; ++kt) {      // cached (h side)
                BFRAG(bb0, bb1, hTc, HT_RS, kt*16);
                uint4 a = wc[(kt*24 + m1)*32 + l];
                if (kt & 1) { MMA(accHx, a, bb0, bb1); } else { MMA(accH, a, bb0, bb1); }
                bool mine = hiW ? (kt >= 8) : (kt < 8);
                if (mine) { uint4 a2 = wc[(kt*24 + m2loc)*32 + l]; MMA(accNh, a2, bb0, bb1); }
            }
            {   // streamed m1 kt14..31 with prefetch
                uint4 p1 = g_decWfrag[(14*48 + mtg1)*32 + l];
                #pragma unroll 1
                for (int kt = 14; kt < 32; ++kt) {
                    uint4 c1 = p1;
                    if (kt < 31) p1 = g_decWfrag[((kt + 1)*48 + mtg1)*32 + l];
                    if (kt < 16) {
                        BFRAG(bb0, bb1, hTc, HT_RS, kt*16);
                        if (kt & 1) { MMA(accHx, c1, bb0, bb1); } else { MMA(accH, c1, bb0, bb1); }
                    } else {
                        BFRAG(bb0, bb1, cT, CT_RS, (kt - 16)*16);
                        if (kt & 1) { MMA(accCx, c1, bb0, bb1); } else { MMA(accC, c1, bb0, bb1); }
                    }
                }
            }
            if (!hiW) {     // m2 comb half kt16..23
                #pragma unroll 1
                for (int kt = 16; kt < 24; ++kt) {
                    uint4 a2 = g_decWfrag[(kt*48 + mtg2)*32 + l];
                    BFRAG(bb0, bb1, cT, CT_RS, (kt - 16)*16);
                    MMA(accNx, a2, bb0, bb1);
                }
            } else {        // m2 h kt14..15 + comb kt24..31
                #pragma unroll
                for (int kt = 14; kt < 16; ++kt) {
                    uint4 a2 = g_decWfrag[(kt*48 + mtg2)*32 + l];
                    BFRAG(bb0, bb1, hTc, HT_RS, kt*16);
                    MMA(accNh, a2, bb0, bb1);
                }
                #pragma unroll 1
                for (int kt = 24; kt < 32; ++kt) {
                    uint4 a2 = g_decWfrag[(kt*48 + mtg2)*32 + l];
                    BFRAG(bb0, bb1, cT, CT_RS, (kt - 16)*16);
                    MMA(accNx, a2, bb0, bb1);
                }
            }
            // epilogue
            int jr = (m1 & 7)*16 + (l >> 2), cb = (l & 3)*2;
            int g = m1 >> 3;   // 0=r, 1=z (full sums)
            *(float2*)&PL[g*1280 + jr*10 + cb]     = make_float2(accH[0]+accHx[0]+accC[0]+accCx[0], accH[1]+accHx[1]+accC[1]+accCx[1]);
            *(float2*)&PL[g*1280 + (jr+8)*10 + cb] = make_float2(accH[2]+accHx[2]+accC[2]+accCx[2], accH[3]+accHx[3]+accC[3]+accCx[3]);
            int jr2 = (w & 7)*16 + (l >> 2);
            if (!hiW) {
                *(float2*)&PL[2*1280 + jr2*10 + cb]     = make_float2(accNh[0], accNh[1]);
                *(float2*)&PL[2*1280 + (jr2+8)*10 + cb] = make_float2(accNh[2], accNh[3]);
                *(float2*)&PL[3*1280 + jr2*10 + cb]     = make_float2(accNx[0], accNx[1]);
                *(float2*)&PL[3*1280 + (jr2+8)*10 + cb] = make_float2(accNx[2], accNx[3]);
            } else {
                *(float2*)&PL[4*1280 + jr2*10 + cb]     = make_float2(accNh[0], accNh[1]);
                *(float2*)&PL[4*1280 + (jr2+8)*10 + cb] = make_float2(accNh[2], accNh[3]);
                *(float2*)&PL[5*1280 + jr2*10 + cb]     = make_float2(accNx[0], accNx[1]);
                *(float2*)&PL[5*1280 + (jr2+8)*10 + cb] = make_float2(accNx[2], accNx[3]);
            }
        }
        __syncthreads();
        {   // GRU update own j's; push h2 to both h-tables
            int jl = tx & 127, j = jbase + jl, pr = tx >> 7;
            #pragma unroll
            for (int q = 0; q < 2; ++q) {
                int b = pr*2 + q;
                float r = sigf(PL[jl*10 + b] + BI[jl]);
                float z = sigf(PL[1280 + jl*10 + b] + BI[128 + jl]);
                float nh = PL[2*1280 + jl*10 + b] + PL[4*1280 + jl*10 + b] + BI[384 + jl];
                float nx = PL[3*1280 + jl*10 + b] + PL[5*1280 + jl*10 + b] + BI[256 + jl];
                float n = tanhf(nx + r*nh);
                float hold = hF[jl*10 + b];
                float h2 = (1.f - z)*n + z*hold;
                hF[jl*10 + b] = h2;
                __half hh = __float2half(h2);
                hTn[b*HT_RS + j] = hh;
                stc16(peerN + (unsigned)(b*HT_RS + j)*2, *(unsigned short*)&hh);
            }
        }
        CLUSTER_SYNC();
        // ---- E: out projection + final linear (both ranks; rank0 writes dout) ----
        if (w < 8) {
            float fin = 0.f;
            #pragma unroll
            for (int f = 0; f < FF; ++f) {
                float acc = 0.f;
                #pragma unroll
                for (int k = l; k < HH; k += 32)
                    acc += __half2float(hTn[w*HT_RS + k]) * outW[f*HH + k];
                #pragma unroll
                for (int o = 16; o; o >>= 1) acc += __shfl_xor_sync(0xffffffffu, acc, o);
                if (l == 0) {
                    float ov = acc + outb[f];
                    hTn[w*HT_RS + 256 + f] = __float2half(ov);
                    fin += ov * linW[f];
                }
            }
            if (l == 0 && rank == 0) dout[(b0 + w)*PP + p] = fin + linb[0];
        }
        __syncthreads();
    }
}

// ---------------- launch ----------------
extern "C" void kernel_launch(void* const* d_in, const int* in_sizes, int n_in,
                              void* d_out, int out_size)
{
    const float* xb   = (const float*)d_in[0];
    const float* eWih = (const float*)d_in[1];
    const float* eWhh = (const float*)d_in[2];
    const float* ebih = (const float*)d_in[3];
    const float* ebhh = (const float*)d_in[4];
    const float* attW = (const float*)d_in[5];
    const float* attb = (const float*)d_in[6];
    const float* dWih = (const float*)d_in[7];
    const float* dWhh = (const float*)d_in[8];
    const float* dbih = (const float*)d_in[9];
    const float* dbhh = (const float*)d_in[10];
    const float* outW = (const float*)d_in[11];
    const float* outb = (const float*)d_in[12];
    const float* linW = (const float*)d_in[13];
    const float* linb = (const float*)d_in[14];
    float* dout = (float*)d_out;

    cudaFuncSetAttribute(k_all, cudaFuncAttributeMaxDynamicSharedMemorySize, SMEM_BYTES);

    k_prep<<<(PREP_N + 255) / 256, 256>>>(eWih, eWhh, dWih, dWhh, attW);
    k_all<<<BB / 4, 512, SMEM_BYTES>>>(xb, ebih, ebhh, attb, dbih, dbhh,
                                       outW, outb, linW, linb, dout);
}

// round 14
// speedup vs baseline: 1.2501x; 1.1023x over previous
#include <cuda_runtime.h>
#include <cuda_fp16.h>
#include <math.h>

#define BB 512
#define SS 336
#define FF 16
#define HH 256
#define PP 48
#define AK 272   // HH+FF

// ---------------- fragment-major prepared weights (device globals) ----------------
__device__ uint4 g_encWfrag[16*48*32];   // enc Whh  (393 KB)
__device__ uint4 g_encIfrag[   48*32];   // enc Wih  (24 KB, single ktile K=16)
__device__ uint4 g_decWfrag[32*48*32];   // dec [Whh | Wih] kt<16 / kt>=16 (786 KB)
__device__ uint4 g_attfrag [17*21*32];   // att_W 336x272 (183 KB)
__device__ __half g_eoutH[(size_t)BB*SS*HH]; // encoder outputs fp16 (88 MB)

__device__ __forceinline__ float sigf(float x) { return 1.f / (1.f + __expf(-x)); }
__device__ __forceinline__ unsigned int pk2(float a, float b) {
    __half2 h = __floats2half2_rn(a, b);
    return *reinterpret_cast<unsigned int*>(&h);
}

// ---------------- prep: build all fragments ----------------
#define N_ENCW (16*48*32)
#define N_ENCI (48*32)
#define N_DECW (32*48*32)
#define N_ATT  (17*21*32)
#define PREP_N (N_ENCW + N_ENCI + N_DECW + N_ATT)

__global__ void k_prep(const float* __restrict__ eWih, const float* __restrict__ eWhh,
                       const float* __restrict__ dWih, const float* __restrict__ dWhh,
                       const float* __restrict__ attW)
{
    int idx = blockIdx.x * 256 + threadIdx.x;
    if (idx >= PREP_N) return;
    const float* src; uint4* dst; int mt, l, c0, ldk;
    if (idx < N_ENCW) {
        int kt = idx / 1536, r = idx % 1536; mt = r / 32; l = r % 32;
        c0 = kt*16 + (l & 3)*2; src = eWhh; ldk = HH; dst = &g_encWfrag[idx];
    } else if (idx < N_ENCW + N_ENCI) {
        int i = idx - N_ENCW; mt = i / 32; l = i % 32;
        c0 = (l & 3)*2; src = eWih; ldk = FF; dst = &g_encIfrag[i];
    } else if (idx < N_ENCW + N_ENCI + N_DECW) {
        int i = idx - N_ENCW - N_ENCI;
        int kt = i / 1536, r = i % 1536; mt = r / 32; l = r % 32;
        if (kt < 16) { src = dWhh; c0 = kt*16 + (l & 3)*2; }
        else         { src = dWih; c0 = (kt - 16)*16 + (l & 3)*2; }
        ldk = HH; dst = &g_decWfrag[i];
    } else {
        int i = idx - N_ENCW - N_ENCI - N_DECW;
        int kt = i / 672, r = i % 672; mt = r / 32; l = r % 32;
        c0 = kt*16 + (l & 3)*2; src = attW; ldk = AK; dst = &g_attfrag[i];
    }
    int mlo = mt*16 + (l >> 2), mhi = mlo + 8;
    uint4 o;
    o.x = pk2(src[mlo*ldk + c0],     src[mlo*ldk + c0 + 1]);
    o.y = pk2(src[mhi*ldk + c0],     src[mhi*ldk + c0 + 1]);
    o.z = pk2(src[mlo*ldk + c0 + 8], src[mlo*ldk + c0 + 9]);
    o.w = pk2(src[mhi*ldk + c0 + 8], src[mhi*ldk + c0 + 9]);
    *dst = o;
}

// ---------------- mma / cluster helpers ----------------
#define MMA(d, a, bb0, bb1) \
    asm volatile("mma.sync.aligned.m16n8k16.row.col.f32.f16.f16.f32 " \
        "{%0,%1,%2,%3}, {%4,%5,%6,%7}, {%8,%9}, {%0,%1,%2,%3};" \
        : "+f"(d[0]), "+f"(d[1]), "+f"(d[2]), "+f"(d[3]) \
        : "r"((a).x), "r"((a).y), "r"((a).z), "r"((a).w), "r"(bb0), "r"(bb1))

#define BFRAG(bb0, bb1, tb, RS, kbase) { \
    const __half* tp_ = (tb) + (l >> 2)*(RS) + (kbase) + (l & 3)*2; \
    bb0 = *(const unsigned int*)tp_; \
    bb1 = *(const unsigned int*)(tp_ + 8); }

__device__ __forceinline__ unsigned int smem_u32(const void* p) {
    unsigned int a;
    asm("{ .reg .u64 t; cvta.to.shared.u64 t, %1; cvt.u32.u64 %0, t; }" : "=r"(a) : "l"(p));
    return a;
}
__device__ __forceinline__ unsigned int mapa32(unsigned int a, unsigned int r) {
    unsigned int o; asm("mapa.shared::cluster.u32 %0, %1, %2;" : "=r"(o) : "r"(a), "r"(r)); return o;
}
__device__ __forceinline__ void stc16(unsigned int a, unsigned short v) {
    asm volatile("st.shared::cluster.u16 [%0], %1;" :: "r"(a), "h"(v));
}
__device__ __forceinline__ void stc32(unsigned int a, unsigned int v) {
    asm volatile("st.shared::cluster.u32 [%0], %1;" :: "r"(a), "r"(v));
}
#define CLUSTER_SYNC() do { \
    asm volatile("barrier.cluster.arrive.aligned;" ::: "memory"); \
    asm volatile("barrier.cluster.wait.aligned;"   ::: "memory"); } while (0)

// smem layout (bytes)
#define WC_SLOTS 14
#define OFF_WC 0                          // 14*24*32*16 = 172032
#define OFF_PL 172032                     // planes (stride-10) / scores / scratch: 20480
#define OFF_HF 192512                     // f32 own-j hold [128][10]: 5120
#define OFF_HT 197632                     // fp16 h tables, 2 bufs x 8x312: 9984
#define OFF_CT 207616                     // fp16 comb [8][280]: 4480
#define OFF_BI 212096                     // f32 own-j biases [4][128]: 2048
#define OFF_AB 214144                     // f32 attb [336]: 1344
#define SMEM_BYTES 215552
#define HT_RS 312
#define CT_RS 280

__global__ __launch_bounds__(512, 1) __cluster_dims__(2, 1, 1)
void k_all(
    const float* __restrict__ xb,
    const float* __restrict__ ebih, const float* __restrict__ ebhh,
    const float* __restrict__ attb,
    const float* __restrict__ dbih, const float* __restrict__ dbhh,
    const float* __restrict__ outW, const float* __restrict__ outb,
    const float* __restrict__ linW, const float* __restrict__ linb,
    float* __restrict__ dout)
{
    extern __shared__ char smx[];
    uint4*  wc   = (uint4*)(smx + OFF_WC);
    float*  PL   = (float*)(smx + OFF_PL);
    float*  SCR  = (float*)(smx + OFF_PL + 12288);
    float*  hF   = (float*)(smx + OFF_HF);
    __half* hTb0 = (__half*)(smx + OFF_HT);
    __half* hTb1 = (__half*)(smx + OFF_HT + 4992);
    __half* cT   = (__half*)(smx + OFF_CT);
    float*  BI   = (float*)(smx + OFF_BI);
    float*  AB   = (float*)(smx + OFF_AB);

    int tx = threadIdx.x, l = tx & 31, w = tx >> 5;
    unsigned int rank; asm("mov.u32 %0, %%cluster_ctarank;" : "=r"(rank));
    int b0 = (blockIdx.x >> 1) * 8;
    int jbase = (int)rank << 7;
    bool hv = (w < 8);
    int m1 = w, m2 = 16 + w;
    int mtg1 = (m1 >> 3)*16 + (int)rank*8 + (m1 & 7);
    int mtg2 = 32 + (int)rank*8 + (m2 & 7);

    unsigned int peerHT0 = mapa32(smem_u32(hTb0), rank ^ 1u);
    unsigned int peerHT1 = mapa32(smem_u32(hTb1), rank ^ 1u);
    unsigned int peerCT  = mapa32(smem_u32(cT),  rank ^ 1u);

    // ---- init: encoder weight cache (kt 0..12 + x slot 13), biases, state ----
    for (int e = tx; e < WC_SLOTS*768; e += 512) {
        int slot = e / 768, m = (e % 768) >> 5, ll = e & 31;
        int mtg = (m >> 3)*16 + (int)rank*8 + (m & 7);
        if (slot < 13)       wc[e] = g_encWfrag[(slot*48 + mtg)*32 + ll];
        else if (slot == 13) wc[e] = g_encIfrag[mtg*32 + ll];
    }
    if (tx < 128) {
        BI[tx]       = ebih[jbase + tx]        + ebhh[jbase + tx];
        BI[128 + tx] = ebih[HH + jbase + tx]   + ebhh[HH + jbase + tx];
        BI[256 + tx] = ebih[2*HH + jbase + tx];
        BI[384 + tx] = ebhh[2*HH + jbase + tx];
    }
    for (int e = tx; e < 1280; e += 512) hF[e] = 0.f;
    for (int e = tx; e < 8*HT_RS; e += 512) hTb0[e] = __float2half(0.f);
    __syncthreads();
    if (tx < 128) { int b = tx >> 4, f = tx & 15;
        hTb0[b*HT_RS + 256 + f] = __float2half(xb[((b0 + b)*SS + 0)*FF + f]); }
    CLUSTER_SYNC();

    // ================= ENCODER =================
    for (int s = 0; s < SS; ++s) {
        const __half* hTc = (s & 1) ? hTb1 : hTb0;
        __half*       hTn = (s & 1) ? hTb0 : hTb1;
        unsigned int peerN = (s & 1) ? peerHT0 : peerHT1;

        float accA0[4] = {}, accA1[4] = {}, accB0[4] = {}, accB1[4] = {};
        unsigned int bb0, bb1;
        uint4 s1a[3], s2a[3];
        #pragma unroll
        for (int i2 = 0; i2 < 3; ++i2) {
            s1a[i2] = g_encWfrag[((13 + i2)*48 + mtg1)*32 + l];
            if (hv) s2a[i2] = g_encWfrag[((13 + i2)*48 + mtg2)*32 + l];
        }
        #pragma unroll
        for (int kt = 0; kt < 13; ++kt) {
            BFRAG(bb0, bb1, hTc, HT_RS, kt*16);
            uint4 a = wc[(kt*24 + m1)*32 + l];
            MMA(accA0, a, bb0, bb1);
            if (hv) { uint4 a2 = wc[(kt*24 + m2)*32 + l]; MMA(accA1, a2, bb0, bb1); }
        }
        #pragma unroll
        for (int i2 = 0; i2 < 3; ++i2) {
            BFRAG(bb0, bb1, hTc, HT_RS, (13 + i2)*16);
            MMA(accA0, s1a[i2], bb0, bb1);
            if (hv) MMA(accA1, s2a[i2], bb0, bb1);
        }
        {   // x tile (k 256..271 of h-table)
            BFRAG(bb0, bb1, hTc, HT_RS, 256);
            uint4 a = wc[(13*24 + m1)*32 + l];  MMA(accB0, a, bb0, bb1);
            if (hv) { uint4 a2 = wc[(13*24 + m2)*32 + l]; MMA(accB1, a2, bb0, bb1); }
        }
        {   // epilogue to gate planes (stride 10)
            int jr = (m1 & 7)*16 + (l >> 2), cb = (l & 3)*2;
            int g = m1 >> 3;
            *(float2*)&PL[(g*128 + jr)*10 + cb]     = make_float2(accA0[0]+accB0[0], accA0[1]+accB0[1]);
            *(float2*)&PL[(g*128 + jr + 8)*10 + cb] = make_float2(accA0[2]+accB0[2], accA0[3]+accB0[3]);
            if (hv) {
                int jr2 = (m2 & 7)*16 + (l >> 2);
                *(float2*)&PL[(256 + jr2)*10 + cb]     = make_float2(accA1[0], accA1[1]);
                *(float2*)&PL[(256 + jr2 + 8)*10 + cb] = make_float2(accA1[2], accA1[3]);
                *(float2*)&PL[(384 + jr2)*10 + cb]     = make_float2(accB1[0], accB1[1]);
                *(float2*)&PL[(384 + jr2 + 8)*10 + cb] = make_float2(accB1[2], accB1[3]);
            }
        }
        __syncthreads();
        {   // GRU update: own 128 j's; push h2 to both h-tables
            int jl = tx & 127, j = jbase + jl, pr = tx >> 7;
            #pragma unroll
            for (int q = 0; q < 2; ++q) {
                int b = pr*2 + q;
                float r = sigf(PL[jl*10 + b] + BI[jl]);
                float z = sigf(PL[(128 + jl)*10 + b] + BI[128 + jl]);
                float n = tanhf(PL[(384 + jl)*10 + b] + BI[256 + jl]
                              + r*(PL[(256 + jl)*10 + b] + BI[384 + jl]));
                float hold = hF[jl*10 + b];
                float h2 = (1.f - z)*n + z*hold;
                hF[jl*10 + b] = h2;
                __half hh = __float2half(h2);
                hTn[b*HT_RS + j] = hh;
                stc16(peerN + (unsigned)(b*HT_RS + j)*2, *(unsigned short*)&hh);
                g_eoutH[((size_t)(b0 + b)*SS + s)*HH + j] = hh;
            }
            if (tx < 128 && s + 1 < SS) { int b = tx >> 4, f = tx & 15;
                hTn[b*HT_RS + 256 + f] = __float2half(xb[((b0 + b)*SS + s + 1)*FF + f]); }
        }
        CLUSTER_SYNC();
    }

    // ================= DECODER setup =================
    for (int e = tx; e < WC_SLOTS*768; e += 512) {
        int slot = e / 768, m = (e % 768) >> 5, ll = e & 31;
        int mtg = (m >> 3)*16 + (int)rank*8 + (m & 7);
        wc[e] = g_decWfrag[(slot*48 + mtg)*32 + ll];
    }
    if (tx < 128) {
        BI[tx]       = dbih[jbase + tx]        + dbhh[jbase + tx];
        BI[128 + tx] = dbih[HH + jbase + tx]   + dbhh[HH + jbase + tx];
        BI[256 + tx] = dbih[2*HH + jbase + tx];
        BI[384 + tx] = dbhh[2*HH + jbase + tx];
    }
    for (int e = tx; e < SS; e += 512) AB[e] = attb[e];
    if (tx < 128) { int b = tx >> 4, f = tx & 15;
        hTb0[b*HT_RS + 256 + f] = __float2half(xb[((b0 + b)*SS + (SS - 1))*FF + f]); }
    __syncthreads();

    for (int p = 0; p < PP; ++p) {
        const __half* hTc = (p & 1) ? hTb1 : hTb0;
        __half*       hTn = (p & 1) ? hTb0 : hTb1;
        unsigned int peerN = (p & 1) ? peerHT0 : peerHT1;

        // ---- A: attention scores (both ranks compute all 336) ----
        {
            float ac0[4] = {}, ac1[4] = {};
            unsigned int bb0, bb1;
            bool two = (w < 5);
            uint4 p1 = g_attfrag[(0*21 + w)*32 + l], p2 = p1;
            if (two) p2 = g_attfrag[(0*21 + 16 + w)*32 + l];
            #pragma unroll 1
            for (int kt = 0; kt < 17; ++kt) {
                uint4 c1 = p1, c2 = p2;
                if (kt < 16) {
                    p1 = g_attfrag[((kt + 1)*21 + w)*32 + l];
                    if (two) p2 = g_attfrag[((kt + 1)*21 + 16 + w)*32 + l];
                }
                BFRAG(bb0, bb1, hTc, HT_RS, kt*16);
                MMA(ac0, c1, bb0, bb1);
                if (two) MMA(ac1, c2, bb0, bb1);
            }
            int cb = (l & 3)*2, ro = l >> 2;
            int sr = w*16 + ro;
            *(float2*)&PL[sr*8 + cb]       = make_float2(ac0[0] + AB[sr],     ac0[1] + AB[sr]);
            *(float2*)&PL[(sr + 8)*8 + cb] = make_float2(ac0[2] + AB[sr + 8], ac0[3] + AB[sr + 8]);
            if (two) {
                int sr2 = (16 + w)*16 + ro;
                *(float2*)&PL[sr2*8 + cb]       = make_float2(ac1[0] + AB[sr2],     ac1[1] + AB[sr2]);
                *(float2*)&PL[(sr2 + 8)*8 + cb] = make_float2(ac1[2] + AB[sr2 + 8], ac1[3] + AB[sr2 + 8]);
            }
        }
        __syncthreads();
        // ---- B: softmax (warp = batch row) ----
        if (w < 8) {
            float mx = -1e30f;
            for (int i = l; i < SS; i += 32) mx = fmaxf(mx, PL[i*8 + w]);
            #pragma unroll
            for (int o = 16; o; o >>= 1) mx = fmaxf(mx, __shfl_xor_sync(0xffffffffu, mx, o));
            float sum = 0.f;
            for (int i = l; i < SS; i += 32) {
                float e = __expf(PL[i*8 + w] - mx);
                PL[i*8 + w] = e; sum += e;
            }
            #pragma unroll
            for (int o = 16; o; o >>= 1) sum += __shfl_xor_sync(0xffffffffu, sum, o);
            float inv = 1.f / sum;
            for (int i = l; i < SS; i += 32) PL[i*8 + w] *= inv;
        }
        __syncthreads();
        // ---- C: combine own 128 h-cols; write cT to both ranks ----
        {
            int b = tx >> 6, t = tx & 63, shalf = t >> 5, cq = t & 31;
            const uint2* ep = (const uint2*)(g_eoutH + (size_t)(b0 + b)*SS*HH) + (int)rank*32 + cq;
            float c0 = 0, c1 = 0, c2 = 0, c3 = 0;
            int s0 = shalf*168;
            #pragma unroll 8
            for (int s2 = s0; s2 < s0 + 168; ++s2) {
                float a = PL[s2*8 + b];
                uint2 u = ep[(size_t)s2*64];
                float2 f01 = __half22float2(*(__half2*)&u.x);
                float2 f23 = __half22float2(*(__half2*)&u.y);
                c0 += a*f01.x; c1 += a*f01.y; c2 += a*f23.x; c3 += a*f23.y;
            }
            if (shalf) *(float4*)&SCR[(b*32 + cq)*4] = make_float4(c0, c1, c2, c3);
            __syncthreads();
            if (!shalf) {
                float4 pv = *(float4*)&SCR[(b*32 + cq)*4];
                c0 += pv.x; c1 += pv.y; c2 += pv.z; c3 += pv.w;
                __half2 lo = __floats2half2_rn(c0, c1), hi = __floats2half2_rn(c2, c3);
                int col = jbase + cq*4;
                *(__half2*)&cT[b*CT_RS + col]     = lo;
                *(__half2*)&cT[b*CT_RS + col + 2] = hi;
                unsigned int ad = peerCT + (unsigned)(b*CT_RS + col)*2;
                stc32(ad,     *(unsigned int*)&lo);
                stc32(ad + 4, *(unsigned int*)&hi);
            }
        }
        CLUSTER_SYNC();
        // ---- D: decoder GRU mma (kt<16: Whh x h; kt>=16: Wih x comb) ----
        {
            float accA0[4] = {}, accA1[4] = {}, accB0[4] = {}, accB1[4] = {};
            unsigned int bb0, bb1;
            #pragma unroll
            for (int kt = 0; kt < 14; ++kt) {
                BFRAG(bb0, bb1, hTc, HT_RS, kt*16);
                uint4 a = wc[(kt*24 + m1)*32 + l];
                MMA(accA0, a, bb0, bb1);
                if (hv) { uint4 a2 = wc[(kt*24 + m2)*32 + l]; MMA(accA1, a2, bb0, bb1); }
            }
            uint4 p1 = g_decWfrag[(14*48 + mtg1)*32 + l], p2 = p1;
            if (hv) p2 = g_decWfrag[(14*48 + mtg2)*32 + l];
            #pragma unroll 1
            for (int kt = 14; kt < 32; ++kt) {
                uint4 c1 = p1, c2 = p2;
                if (kt < 31) {
                    p1 = g_decWfrag[((kt + 1)*48 + mtg1)*32 + l];
                    if (hv) p2 = g_decWfrag[((kt + 1)*48 + mtg2)*32 + l];
                }
                if (kt < 16) {
                    BFRAG(bb0, bb1, hTc, HT_RS, kt*16);
                    MMA(accA0, c1, bb0, bb1);
                    if (hv) MMA(accA1, c2, bb0, bb1);
                } else {
                    BFRAG(bb0, bb1, cT, CT_RS, (kt - 16)*16);
                    MMA(accB0, c1, bb0, bb1);
                    if (hv) MMA(accB1, c2, bb0, bb1);
                }
            }
            int jr = (m1 & 7)*16 + (l >> 2), cb = (l & 3)*2;
            int g = m1 >> 3;
            *(float2*)&PL[(g*128 + jr)*10 + cb]     = make_float2(accA0[0]+accB0[0], accA0[1]+accB0[1]);
            *(float2*)&PL[(g*128 + jr + 8)*10 + cb] = make_float2(accA0[2]+accB0[2], accA0[3]+accB0[3]);
            if (hv) {
                int jr2 = (m2 & 7)*16 + (l >> 2);
                *(float2*)&PL[(256 + jr2)*10 + cb]     = make_float2(accA1[0], accA1[1]);
                *(float2*)&PL[(256 + jr2 + 8)*10 + cb] = make_float2(accA1[2], accA1[3]);
                *(float2*)&PL[(384 + jr2)*10 + cb]     = make_float2(accB1[0], accB1[1]);
                *(float2*)&PL[(384 + jr2 + 8)*10 + cb] = make_float2(accB1[2], accB1[3]);
            }
        }
        __syncthreads();
        {   // GRU update own j's; push h2 to both h-tables
            int jl = tx & 127, j = jbase + jl, pr = tx >> 7;
            #pragma unroll
            for (int q = 0; q < 2; ++q) {
                int b = pr*2 + q;
                float r = sigf(PL[jl*10 + b] + BI[jl]);
                float z = sigf(PL[(128 + jl)*10 + b] + BI[128 + jl]);
                float n = tanhf(PL[(384 + jl)*10 + b] + BI[256 + jl]
                              + r*(PL[(256 + jl)*10 + b] + BI[384 + jl]));
                float hold = hF[jl*10 + b];
                float h2 = (1.f - z)*n + z*hold;
                hF[jl*10 + b] = h2;
                __half hh = __float2half(h2);
                hTn[b*HT_RS + j] = hh;
                stc16(peerN + (unsigned)(b*HT_RS + j)*2, *(unsigned short*)&hh);
            }
        }
        CLUSTER_SYNC();
        // ---- E: out projection + final linear (both ranks; rank0 writes dout) ----
        if (w < 8) {
            float fin = 0.f;
            #pragma unroll
            for (int f = 0; f < FF; ++f) {
                float acc = 0.f;
                #pragma unroll
                for (int k = l; k < HH; k += 32)
                    acc += __half2float(hTn[w*HT_RS + k]) * outW[f*HH + k];
                #pragma unroll
                for (int o = 16; o; o >>= 1) acc += __shfl_xor_sync(0xffffffffu, acc, o);
                if (l == 0) {
                    float ov = acc + outb[f];
                    hTn[w*HT_RS + 256 + f] = __float2half(ov);
                    fin += ov * linW[f];
                }
            }
            if (l == 0 && rank == 0) dout[(b0 + w)*PP + p] = fin + linb[0];
        }
        __syncthreads();
    }
}

// ---------------- launch ----------------
extern "C" void kernel_launch(void* const* d_in, const int* in_sizes, int n_in,
                              void* d_out, int out_size)
{
    const float* xb   = (const float*)d_in[0];
    const float* eWih = (const float*)d_in[1];
    const float* eWhh = (const float*)d_in[2];
    const float* ebih = (const float*)d_in[3];
    const float* ebhh = (const float*)d_in[4];
    const float* attW = (const float*)d_in[5];
    const float* attb = (const float*)d_in[6];
    const float* dWih = (const float*)d_in[7];
    const float* dWhh = (const float*)d_in[8];
    const float* dbih = (const float*)d_in[9];
    const float* dbhh = (const float*)d_in[10];
    const float* outW = (const float*)d_in[11];
    const float* outb = (const float*)d_in[12];
    const float* linW = (const float*)d_in[13];
    const float* linb = (const float*)d_in[14];
    float* dout = (float*)d_out;

    cudaFuncSetAttribute(k_all, cudaFuncAttributeMaxDynamicSharedMemorySize, SMEM_BYTES);

    k_prep<<<(PREP_N + 255) / 256, 256>>>(eWih, eWhh, dWih, dWhh, attW);
    k_all<<<BB / 4, 512, SMEM_BYTES>>>(xb, ebih, ebhh, attb, dbih, dbhh,
                                       outW, outb, linW, linb, dout);
}

// round 15
// speedup vs baseline: 1.2725x; 1.0180x over previous
#include <cuda_runtime.h>
#include <cuda_fp16.h>
#include <math.h>

#define BB 512
#define SS 336
#define FF 16
#define HH 256
#define PP 48
#define AK 272   // HH+FF

// ---------------- fragment-major prepared weights (device globals) ----------------
__device__ uint4 g_encWfrag[16*48*32];   // enc Whh  (393 KB)
__device__ uint4 g_encIfrag[   48*32];   // enc Wih  (24 KB, single ktile K=16)
__device__ uint4 g_decWfrag[32*48*32];   // dec [Whh | Wih] kt<16 / kt>=16 (786 KB)
__device__ uint4 g_attfrag [17*21*32];   // att_W 336x272 (183 KB)
__device__ __half g_eoutH[(size_t)BB*SS*HH]; // encoder outputs fp16 (88 MB)

__device__ __forceinline__ float sigf(float x) { return 1.f / (1.f + __expf(-x)); }
__device__ __forceinline__ unsigned int pk2(float a, float b) {
    __half2 h = __floats2half2_rn(a, b);
    return *reinterpret_cast<unsigned int*>(&h);
}

// ---------------- prep: build all fragments ----------------
#define N_ENCW (16*48*32)
#define N_ENCI (48*32)
#define N_DECW (32*48*32)
#define N_ATT  (17*21*32)
#define PREP_N (N_ENCW + N_ENCI + N_DECW + N_ATT)

__global__ void k_prep(const float* __restrict__ eWih, const float* __restrict__ eWhh,
                       const float* __restrict__ dWih, const float* __restrict__ dWhh,
                       const float* __restrict__ attW)
{
    int idx = blockIdx.x * 256 + threadIdx.x;
    if (idx >= PREP_N) return;
    const float* src; uint4* dst; int mt, l, c0, ldk;
    if (idx < N_ENCW) {
        int kt = idx / 1536, r = idx % 1536; mt = r / 32; l = r % 32;
        c0 = kt*16 + (l & 3)*2; src = eWhh; ldk = HH; dst = &g_encWfrag[idx];
    } else if (idx < N_ENCW + N_ENCI) {
        int i = idx - N_ENCW; mt = i / 32; l = i % 32;
        c0 = (l & 3)*2; src = eWih; ldk = FF; dst = &g_encIfrag[i];
    } else if (idx < N_ENCW + N_ENCI + N_DECW) {
        int i = idx - N_ENCW - N_ENCI;
        int kt = i / 1536, r = i % 1536; mt = r / 32; l = r % 32;
        if (kt < 16) { src = dWhh; c0 = kt*16 + (l & 3)*2; }
        else         { src = dWih; c0 = (kt - 16)*16 + (l & 3)*2; }
        ldk = HH; dst = &g_decWfrag[i];
    } else {
        int i = idx - N_ENCW - N_ENCI - N_DECW;
        int kt = i / 672, r = i % 672; mt = r / 32; l = r % 32;
        c0 = kt*16 + (l & 3)*2; src = attW; ldk = AK; dst = &g_attfrag[i];
    }
    int mlo = mt*16 + (l >> 2), mhi = mlo + 8;
    uint4 o;
    o.x = pk2(src[mlo*ldk + c0],     src[mlo*ldk + c0 + 1]);
    o.y = pk2(src[mhi*ldk + c0],     src[mhi*ldk + c0 + 1]);
    o.z = pk2(src[mlo*ldk + c0 + 8], src[mlo*ldk + c0 + 9]);
    o.w = pk2(src[mhi*ldk + c0 + 8], src[mhi*ldk + c0 + 9]);
    *dst = o;
}

// ---------------- mma / cluster helpers ----------------
#define MMA(d, a, bb0, bb1) \
    asm volatile("mma.sync.aligned.m16n8k16.row.col.f32.f16.f16.f32 " \
        "{%0,%1,%2,%3}, {%4,%5,%6,%7}, {%8,%9}, {%0,%1,%2,%3};" \
        : "+f"(d[0]), "+f"(d[1]), "+f"(d[2]), "+f"(d[3]) \
        : "r"((a).x), "r"((a).y), "r"((a).z), "r"((a).w), "r"(bb0), "r"(bb1))

#define BFRAG(bb0, bb1, tb, RS, kbase) { \
    const __half* tp_ = (tb) + (l >> 2)*(RS) + (kbase) + (l & 3)*2; \
    bb0 = *(const unsigned int*)tp_; \
    bb1 = *(const unsigned int*)(tp_ + 8); }

__device__ __forceinline__ unsigned int smem_u32(const void* p) {
    unsigned int a;
    asm("{ .reg .u64 t; cvta.to.shared.u64 t, %1; cvt.u32.u64 %0, t; }" : "=r"(a) : "l"(p));
    return a;
}
__device__ __forceinline__ unsigned int mapa32(unsigned int a, unsigned int r) {
    unsigned int o; asm("mapa.shared::cluster.u32 %0, %1, %2;" : "=r"(o) : "r"(a), "r"(r)); return o;
}
__device__ __forceinline__ void stc16(unsigned int a, unsigned short v) {
    asm volatile("st.shared::cluster.u16 [%0], %1;" :: "r"(a), "h"(v));
}
__device__ __forceinline__ void stc32(unsigned int a, unsigned int v) {
    asm volatile("st.shared::cluster.u32 [%0], %1;" :: "r"(a), "r"(v));
}
#define CLUSTER_SYNC() do { \
    asm volatile("barrier.cluster.arrive.aligned;" ::: "memory"); \
    asm volatile("barrier.cluster.wait.aligned;"   ::: "memory"); } while (0)

// ---- encoder step sync: st.async data-carrying exchange + mbarrier ----
__device__ __forceinline__ void mbar_init(unsigned int a, unsigned int cnt) {
    asm volatile("mbarrier.init.shared.b64 [%0], %1;" :: "r"(a), "r"(cnt) : "memory");
}
__device__ __forceinline__ void mbar_expect(unsigned int a, unsigned int bytes) {
    asm volatile("mbarrier.arrive.expect_tx.shared.b64 _, [%0], %1;" :: "r"(a), "r"(bytes) : "memory");
}
__device__ __forceinline__ void stasync32(unsigned int remAddr, unsigned int v, unsigned int remMbar) {
    asm volatile("st.async.shared::cluster.mbarrier::complete_tx::bytes.b32 [%0], %1, [%2];"
                 :: "r"(remAddr), "r"(v), "r"(remMbar) : "memory");
}
__device__ __forceinline__ void mbar_wait(unsigned int a, unsigned int parity) {
    unsigned int done;
    asm volatile("{\n\t.reg .pred p;\n\t"
        "mbarrier.try_wait.parity.acquire.cluster.shared::cta.b64 p, [%1], %2;\n\t"
        "selp.b32 %0, 1, 0, p;\n\t}"
        : "=r"(done) : "r"(a), "r"(parity) : "memory");
    while (!done) {
        asm volatile("{\n\t.reg .pred p;\n\t"
            "mbarrier.try_wait.parity.acquire.cluster.shared::cta.b64 p, [%1], %2;\n\t"
            "selp.b32 %0, 1, 0, p;\n\t}"
            : "=r"(done) : "r"(a), "r"(parity) : "memory");
    }
}

// smem layout (bytes)
#define WC_SLOTS 14
#define OFF_WC 0                          // 14*24*32*16 = 172032
#define OFF_PL 172032                     // planes (stride-10) / scores / scratch: 20480
#define OFF_HF 192512                     // f32 own-j hold [128][10]: 5120
#define OFF_HT 197632                     // fp16 h tables, 2 bufs x 8x312: 9984
#define OFF_CT 207616                     // fp16 comb [8][280]: 4480
#define OFF_BI 212096                     // f32 own-j biases [4][128]: 2048
#define OFF_AB 214144                     // f32 attb [336]: 1344
#define OFF_MB 215552                     // 2 mbarriers: 16
#define SMEM_BYTES 215568
#define HT_RS 312
#define CT_RS 280

__global__ __launch_bounds__(512, 1) __cluster_dims__(2, 1, 1)
void k_all(
    const float* __restrict__ xb,
    const float* __restrict__ ebih, const float* __restrict__ ebhh,
    const float* __restrict__ attb,
    const float* __restrict__ dbih, const float* __restrict__ dbhh,
    const float* __restrict__ outW, const float* __restrict__ outb,
    const float* __restrict__ linW, const float* __restrict__ linb,
    float* __restrict__ dout)
{
    extern __shared__ char smx[];
    uint4*  wc   = (uint4*)(smx + OFF_WC);
    float*  PL   = (float*)(smx + OFF_PL);
    float*  SCR  = (float*)(smx + OFF_PL + 12288);
    float*  hF   = (float*)(smx + OFF_HF);
    __half* hTb0 = (__half*)(smx + OFF_HT);
    __half* hTb1 = (__half*)(smx + OFF_HT + 4992);
    __half* cT   = (__half*)(smx + OFF_CT);
    float*  BI   = (float*)(smx + OFF_BI);
    float*  AB   = (float*)(smx + OFF_AB);

    int tx = threadIdx.x, l = tx & 31, w = tx >> 5;
    unsigned int rank; asm("mov.u32 %0, %%cluster_ctarank;" : "=r"(rank));
    int b0 = (blockIdx.x >> 1) * 8;
    int jbase = (int)rank << 7;
    bool hv = (w < 8);
    int m1 = w, m2 = 16 + w;
    int mtg1 = (m1 >> 3)*16 + (int)rank*8 + (m1 & 7);
    int mtg2 = 32 + (int)rank*8 + (m2 & 7);

    unsigned int peerHT0 = mapa32(smem_u32(hTb0), rank ^ 1u);
    unsigned int peerHT1 = mapa32(smem_u32(hTb1), rank ^ 1u);
    unsigned int peerCT  = mapa32(smem_u32(cT),  rank ^ 1u);
    unsigned int mbL = smem_u32(smx + OFF_MB);
    unsigned int mbP = mapa32(mbL, rank ^ 1u);

    // ---- init: encoder weight cache (kt 0..12 + x slot 13), biases, state ----
    for (int e = tx; e < WC_SLOTS*768; e += 512) {
        int slot = e / 768, m = (e % 768) >> 5, ll = e & 31;
        int mtg = (m >> 3)*16 + (int)rank*8 + (m & 7);
        if (slot < 13)       wc[e] = g_encWfrag[(slot*48 + mtg)*32 + ll];
        else if (slot == 13) wc[e] = g_encIfrag[mtg*32 + ll];
    }
    if (tx == 0) { mbar_init(mbL, 1); mbar_init(mbL + 8, 1); }
    if (tx < 128) {
        BI[tx]       = ebih[jbase + tx]        + ebhh[jbase + tx];
        BI[128 + tx] = ebih[HH + jbase + tx]   + ebhh[HH + jbase + tx];
        BI[256 + tx] = ebih[2*HH + jbase + tx];
        BI[384 + tx] = ebhh[2*HH + jbase + tx];
    }
    for (int e = tx; e < 1280; e += 512) hF[e] = 0.f;
    for (int e = tx; e < 8*HT_RS; e += 512) hTb0[e] = __float2half(0.f);
    __syncthreads();
    if (tx < 128) { int b = tx >> 4, f = tx & 15;
        hTb0[b*HT_RS + 256 + f] = __float2half(xb[((b0 + b)*SS + 0)*FF + f]); }
    CLUSTER_SYNC();

    // ================= ENCODER =================
    for (int s = 0; s < SS; ++s) {
        const __half* hTc = (s & 1) ? hTb1 : hTb0;
        __half*       hTn = (s & 1) ? hTb0 : hTb1;
        unsigned int peerN = (s & 1) ? peerHT0 : peerHT1;
        unsigned int mbuf = (unsigned)(s & 1) << 3;

        float accA0[4] = {}, accA1[4] = {}, accB0[4] = {}, accB1[4] = {};
        unsigned int bb0, bb1;
        uint4 s1a[3], s2a[3];
        #pragma unroll
        for (int i2 = 0; i2 < 3; ++i2) {
            s1a[i2] = g_encWfrag[((13 + i2)*48 + mtg1)*32 + l];
            if (hv) s2a[i2] = g_encWfrag[((13 + i2)*48 + mtg2)*32 + l];
        }
        #pragma unroll
        for (int kt = 0; kt < 13; ++kt) {
            BFRAG(bb0, bb1, hTc, HT_RS, kt*16);
            uint4 a = wc[(kt*24 + m1)*32 + l];
            MMA(accA0, a, bb0, bb1);
            if (hv) { uint4 a2 = wc[(kt*24 + m2)*32 + l]; MMA(accA1, a2, bb0, bb1); }
        }
        #pragma unroll
        for (int i2 = 0; i2 < 3; ++i2) {
            BFRAG(bb0, bb1, hTc, HT_RS, (13 + i2)*16);
            MMA(accA0, s1a[i2], bb0, bb1);
            if (hv) MMA(accA1, s2a[i2], bb0, bb1);
        }
        {   // x tile (k 256..271 of h-table)
            BFRAG(bb0, bb1, hTc, HT_RS, 256);
            uint4 a = wc[(13*24 + m1)*32 + l];  MMA(accB0, a, bb0, bb1);
            if (hv) { uint4 a2 = wc[(13*24 + m2)*32 + l]; MMA(accB1, a2, bb0, bb1); }
        }
        {   // epilogue to gate planes (stride 10)
            int jr = (m1 & 7)*16 + (l >> 2), cb = (l & 3)*2;
            int g = m1 >> 3;
            *(float2*)&PL[(g*128 + jr)*10 + cb]     = make_float2(accA0[0]+accB0[0], accA0[1]+accB0[1]);
            *(float2*)&PL[(g*128 + jr + 8)*10 + cb] = make_float2(accA0[2]+accB0[2], accA0[3]+accB0[3]);
            if (hv) {
                int jr2 = (m2 & 7)*16 + (l >> 2);
                *(float2*)&PL[(256 + jr2)*10 + cb]     = make_float2(accA1[0], accA1[1]);
                *(float2*)&PL[(256 + jr2 + 8)*10 + cb] = make_float2(accA1[2], accA1[3]);
                *(float2*)&PL[(384 + jr2)*10 + cb]     = make_float2(accB1[0], accB1[1]);
                *(float2*)&PL[(384 + jr2 + 8)*10 + cb] = make_float2(accB1[2], accB1[3]);
            }
        }
        __syncthreads();
        {   // GRU update: thread -> (row b, j-pair); st.async pushes carry the sync
            if (tx == 0) mbar_expect(mbL + mbuf, 2048);
            int b = tx >> 6, jp = tx & 63;
            int jl0 = jp*2;
            float h2v[2];
            #pragma unroll
            for (int jj = 0; jj < 2; ++jj) {
                int jl = jl0 + jj;
                float r = sigf(PL[jl*10 + b] + BI[jl]);
                float z = sigf(PL[(128 + jl)*10 + b] + BI[128 + jl]);
                float n = tanhf(PL[(384 + jl)*10 + b] + BI[256 + jl]
                              + r*(PL[(256 + jl)*10 + b] + BI[384 + jl]));
                float hold = hF[jl*10 + b];
                h2v[jj] = (1.f - z)*n + z*hold;
                hF[jl*10 + b] = h2v[jj];
            }
            __half2 hp = __floats2half2_rn(h2v[0], h2v[1]);
            int j0 = jbase + jl0;
            *(__half2*)&hTn[b*HT_RS + j0] = hp;
            stasync32(peerN + (unsigned)(b*HT_RS + j0)*2, *(unsigned int*)&hp, mbP + mbuf);
            *(__half2*)&g_eoutH[((size_t)(b0 + b)*SS + s)*HH + j0] = hp;
            if (tx < 128 && s + 1 < SS) { int bb = tx >> 4, f = tx & 15;
                hTn[bb*HT_RS + 256 + f] = __float2half(xb[((b0 + bb)*SS + s + 1)*FF + f]); }
        }
        __syncthreads();
        mbar_wait(mbL + mbuf, (unsigned)((s >> 1) & 1));
    }

    // ================= DECODER setup =================
    for (int e = tx; e < WC_SLOTS*768; e += 512) {
        int slot = e / 768, m = (e % 768) >> 5, ll = e & 31;
        int mtg = (m >> 3)*16 + (int)rank*8 + (m & 7);
        wc[e] = g_decWfrag[(slot*48 + mtg)*32 + ll];
    }
    if (tx < 128) {
        BI[tx]       = dbih[jbase + tx]        + dbhh[jbase + tx];
        BI[128 + tx] = dbih[HH + jbase + tx]   + dbhh[HH + jbase + tx];
        BI[256 + tx] = dbih[2*HH + jbase + tx];
        BI[384 + tx] = dbhh[2*HH + jbase + tx];
    }
    for (int e = tx; e < SS; e += 512) AB[e] = attb[e];
    if (tx < 128) { int b = tx >> 4, f = tx & 15;
        hTb0[b*HT_RS + 256 + f] = __float2half(xb[((b0 + b)*SS + (SS - 1))*FF + f]); }
    __syncthreads();

    for (int p = 0; p < PP; ++p) {
        const __half* hTc = (p & 1) ? hTb1 : hTb0;
        __half*       hTn = (p & 1) ? hTb0 : hTb1;
        unsigned int peerN = (p & 1) ? peerHT0 : peerHT1;

        // ---- A: attention scores (both ranks compute all 336) ----
        {
            float ac0[4] = {}, ac1[4] = {};
            unsigned int bb0, bb1;
            bool two = (w < 5);
            uint4 p1 = g_attfrag[(0*21 + w)*32 + l], p2 = p1;
            if (two) p2 = g_attfrag[(0*21 + 16 + w)*32 + l];
            #pragma unroll 1
            for (int kt = 0; kt < 17; ++kt) {
                uint4 c1 = p1, c2 = p2;
                if (kt < 16) {
                    p1 = g_attfrag[((kt + 1)*21 + w)*32 + l];
                    if (two) p2 = g_attfrag[((kt + 1)*21 + 16 + w)*32 + l];
                }
                BFRAG(bb0, bb1, hTc, HT_RS, kt*16);
                MMA(ac0, c1, bb0, bb1);
                if (two) MMA(ac1, c2, bb0, bb1);
            }
            int cb = (l & 3)*2, ro = l >> 2;
            int sr = w*16 + ro;
            *(float2*)&PL[sr*8 + cb]       = make_float2(ac0[0] + AB[sr],     ac0[1] + AB[sr]);
            *(float2*)&PL[(sr + 8)*8 + cb] = make_float2(ac0[2] + AB[sr + 8], ac0[3] + AB[sr + 8]);
            if (two) {
                int sr2 = (16 + w)*16 + ro;
                *(float2*)&PL[sr2*8 + cb]       = make_float2(ac1[0] + AB[sr2],     ac1[1] + AB[sr2]);
                *(float2*)&PL[(sr2 + 8)*8 + cb] = make_float2(ac1[2] + AB[sr2 + 8], ac1[3] + AB[sr2 + 8]);
            }
        }
        __syncthreads();
        // ---- B: softmax (warp = batch row) ----
        if (w < 8) {
            float mx = -1e30f;
            for (int i = l; i < SS; i += 32) mx = fmaxf(mx, PL[i*8 + w]);
            #pragma unroll
            for (int o = 16; o; o >>= 1) mx = fmaxf(mx, __shfl_xor_sync(0xffffffffu, mx, o));
            float sum = 0.f;
            for (int i = l; i < SS; i += 32) {
                float e = __expf(PL[i*8 + w] - mx);
                PL[i*8 + w] = e; sum += e;
            }
            #pragma unroll
            for (int o = 16; o; o >>= 1) sum += __shfl_xor_sync(0xffffffffu, sum, o);
            float inv = 1.f / sum;
            for (int i = l; i < SS; i += 32) PL[i*8 + w] *= inv;
        }
        __syncthreads();
        // ---- C: combine own 128 h-cols; write cT to both ranks ----
        {
            int b = tx >> 6, t = tx & 63, shalf = t >> 5, cq = t & 31;
            const uint2* ep = (const uint2*)(g_eoutH + (size_t)(b0 + b)*SS*HH) + (int)rank*32 + cq;
            float c0 = 0, c1 = 0, c2 = 0, c3 = 0;
            int s0 = shalf*168;
            #pragma unroll 8
            for (int s2 = s0; s2 < s0 + 168; ++s2) {
                float a = PL[s2*8 + b];
                uint2 u = ep[(size_t)s2*64];
                float2 f01 = __half22float2(*(__half2*)&u.x);
                float2 f23 = __half22float2(*(__half2*)&u.y);
                c0 += a*f01.x; c1 += a*f01.y; c2 += a*f23.x; c3 += a*f23.y;
            }
            if (shalf) *(float4*)&SCR[(b*32 + cq)*4] = make_float4(c0, c1, c2, c3);
            __syncthreads();
            if (!shalf) {
                float4 pv = *(float4*)&SCR[(b*32 + cq)*4];
                c0 += pv.x; c1 += pv.y; c2 += pv.z; c3 += pv.w;
                __half2 lo = __floats2half2_rn(c0, c1), hi = __floats2half2_rn(c2, c3);
                int col = jbase + cq*4;
                *(__half2*)&cT[b*CT_RS + col]     = lo;
                *(__half2*)&cT[b*CT_RS + col + 2] = hi;
                unsigned int ad = peerCT + (unsigned)(b*CT_RS + col)*2;
                stc32(ad,     *(unsigned int*)&lo);
                stc32(ad + 4, *(unsigned int*)&hi);
            }
        }
        CLUSTER_SYNC();
        // ---- D: decoder GRU mma (kt<16: Whh x h; kt>=16: Wih x comb) ----
        {
            float accA0[4] = {}, accA1[4] = {}, accB0[4] = {}, accB1[4] = {};
            unsigned int bb0, bb1;
            #pragma unroll
            for (int kt = 0; kt < 14; ++kt) {
                BFRAG(bb0, bb1, hTc, HT_RS, kt*16);
                uint4 a = wc[(kt*24 + m1)*32 + l];
                MMA(accA0, a, bb0, bb1);
                if (hv) { uint4 a2 = wc[(kt*24 + m2)*32 + l]; MMA(accA1, a2, bb0, bb1); }
            }
            uint4 p1 = g_decWfrag[(14*48 + mtg1)*32 + l], p2 = p1;
            if (hv) p2 = g_decWfrag[(14*48 + mtg2)*32 + l];
            #pragma unroll 1
            for (int kt = 14; kt < 32; ++kt) {
                uint4 c1 = p1, c2 = p2;
                if (kt < 31) {
                    p1 = g_decWfrag[((kt + 1)*48 + mtg1)*32 + l];
                    if (hv) p2 = g_decWfrag[((kt + 1)*48 + mtg2)*32 + l];
                }
                if (kt < 16) {
                    BFRAG(bb0, bb1, hTc, HT_RS, kt*16);
                    MMA(accA0, c1, bb0, bb1);
                    if (hv) MMA(accA1, c2, bb0, bb1);
                } else {
                    BFRAG(bb0, bb1, cT, CT_RS, (kt - 16)*16);
                    MMA(accB0, c1, bb0, bb1);
                    if (hv) MMA(accB1, c2, bb0, bb1);
                }
            }
            int jr = (m1 & 7)*16 + (l >> 2), cb = (l & 3)*2;
            int g = m1 >> 3;
            *(float2*)&PL[(g*128 + jr)*10 + cb]     = make_float2(accA0[0]+accB0[0], accA0[1]+accB0[1]);
            *(float2*)&PL[(g*128 + jr + 8)*10 + cb] = make_float2(accA0[2]+accB0[2], accA0[3]+accB0[3]);
            if (hv) {
                int jr2 = (m2 & 7)*16 + (l >> 2);
                *(float2*)&PL[(256 + jr2)*10 + cb]     = make_float2(accA1[0], accA1[1]);
                *(float2*)&PL[(256 + jr2 + 8)*10 + cb] = make_float2(accA1[2], accA1[3]);
                *(float2*)&PL[(384 + jr2)*10 + cb]     = make_float2(accB1[0], accB1[1]);
                *(float2*)&PL[(384 + jr2 + 8)*10 + cb] = make_float2(accB1[2], accB1[3]);
            }
        }
        __syncthreads();
        {   // GRU update own j's; push h2 to both h-tables
            int jl = tx & 127, j = jbase + jl, pr = tx >> 7;
            #pragma unroll
            for (int q = 0; q < 2; ++q) {
                int b = pr*2 + q;
                float r = sigf(PL[jl*10 + b] + BI[jl]);
                float z = sigf(PL[(128 + jl)*10 + b] + BI[128 + jl]);
                float n = tanhf(PL[(384 + jl)*10 + b] + BI[256 + jl]
                              + r*(PL[(256 + jl)*10 + b] + BI[384 + jl]));
                float hold = hF[jl*10 + b];
                float h2 = (1.f - z)*n + z*hold;
                hF[jl*10 + b] = h2;
                __half hh = __float2half(h2);
                hTn[b*HT_RS + j] = hh;
                stc16(peerN + (unsigned)(b*HT_RS + j)*2, *(unsigned short*)&hh);
            }
        }
        CLUSTER_SYNC();
        // ---- E: out projection + final linear (both ranks; rank0 writes dout) ----
        if (w < 8) {
            float fin = 0.f;
            #pragma unroll
            for (int f = 0; f < FF; ++f) {
                float acc = 0.f;
                #pragma unroll
                for (int k = l; k < HH; k += 32)
                    acc += __half2float(hTn[w*HT_RS + k]) * outW[f*HH + k];
                #pragma unroll
                for (int o = 16; o; o >>= 1) acc += __shfl_xor_sync(0xffffffffu, acc, o);
                if (l == 0) {
                    float ov = acc + outb[f];
                    hTn[w*HT_RS + 256 + f] = __float2half(ov);
                    fin += ov * linW[f];
                }
            }
            if (l == 0 && rank == 0) dout[(b0 + w)*PP + p] = fin + linb[0];
        }
        __syncthreads();
    }
}

// ---------------- launch ----------------
extern "C" void kernel_launch(void* const* d_in, const int* in_sizes, int n_in,
                              void* d_out, int out_size)
{
    const float* xb   = (const float*)d_in[0];
    const float* eWih = (const float*)d_in[1];
    const float* eWhh = (const float*)d_in[2];
    const float* ebih = (const float*)d_in[3];
    const float* ebhh = (const float*)d_in[4];
    const float* attW = (const float*)d_in[5];
    const float* attb = (const float*)d_in[6];
    const float* dWih = (const float*)d_in[7];
    const float* dWhh = (const float*)d_in[8];
    const float* dbih = (const float*)d_in[9];
    const float* dbhh = (const float*)d_in[10];
    const float* outW = (const float*)d_in[11];
    const float* outb = (const float*)d_in[12];
    const float* linW = (const float*)d_in[13];
    const float* linb = (const float*)d_in[14];
    float* dout = (float*)d_out;

    cudaFuncSetAttribute(k_all, cudaFuncAttributeMaxDynamicSharedMemorySize, SMEM_BYTES);

    k_prep<<<(PREP_N + 255) / 256, 256>>>(eWih, eWhh, dWih, dWhh, attW);
    k_all<<<BB / 4, 512, SMEM_BYTES>>>(xb, ebih, ebhh, attb, dbih, dbhh,
                                       outW, outb, linW, linb, dout);
}

// round 16
// speedup vs baseline: 1.3237x; 1.0402x over previous
#include <cuda_runtime.h>
#include <cuda_fp16.h>
#include <math.h>

#define BB 512
#define SS 336
#define FF 16
#define HH 256
#define PP 48
#define AK 272   // HH+FF

// ---------------- fragment-major prepared weights (device globals) ----------------
__device__ uint4 g_encWfrag[16*48*32];   // enc Whh  (393 KB)
__device__ uint4 g_encIfrag[   48*32];   // enc Wih  (24 KB, single ktile K=16)
__device__ uint4 g_decWfrag[32*48*32];   // dec [Whh | Wih] kt<16 / kt>=16 (786 KB)
__device__ uint4 g_attfrag [17*21*32];   // att_W 336x272 (183 KB)
__device__ __half g_eoutH[(size_t)BB*SS*HH]; // encoder outputs fp16 (88 MB)

__device__ __forceinline__ float sigf(float x) { return 1.f / (1.f + __expf(-x)); }
// fast tanh via exp2-based __expf: tanh(x) = 1 - 2/(e^{2x}+1)
// safe at both extremes (x->+inf: 1; x->-inf: -1), rel err ~1e-7
__device__ __forceinline__ float tanhfast(float x) {
    return 1.f - 2.f / (__expf(2.f * x) + 1.f);
}
__device__ __forceinline__ unsigned int pk2(float a, float b) {
    __half2 h = __floats2half2_rn(a, b);
    return *reinterpret_cast<unsigned int*>(&h);
}

// ---------------- prep: build all fragments ----------------
#define N_ENCW (16*48*32)
#define N_ENCI (48*32)
#define N_DECW (32*48*32)
#define N_ATT  (17*21*32)
#define PREP_N (N_ENCW + N_ENCI + N_DECW + N_ATT)

__global__ void k_prep(const float* __restrict__ eWih, const float* __restrict__ eWhh,
                       const float* __restrict__ dWih, const float* __restrict__ dWhh,
                       const float* __restrict__ attW)
{
    int idx = blockIdx.x * 256 + threadIdx.x;
    if (idx >= PREP_N) return;
    const float* src; uint4* dst; int mt, l, c0, ldk;
    if (idx < N_ENCW) {
        int kt = idx / 1536, r = idx % 1536; mt = r / 32; l = r % 32;
        c0 = kt*16 + (l & 3)*2; src = eWhh; ldk = HH; dst = &g_encWfrag[idx];
    } else if (idx < N_ENCW + N_ENCI) {
        int i = idx - N_ENCW; mt = i / 32; l = i % 32;
        c0 = (l & 3)*2; src = eWih; ldk = FF; dst = &g_encIfrag[i];
    } else if (idx < N_ENCW + N_ENCI + N_DECW) {
        int i = idx - N_ENCW - N_ENCI;
        int kt = i / 1536, r = i % 1536; mt = r / 32; l = r % 32;
        if (kt < 16) { src = dWhh; c0 = kt*16 + (l & 3)*2; }
        else         { src = dWih; c0 = (kt - 16)*16 + (l & 3)*2; }
        ldk = HH; dst = &g_decWfrag[i];
    } else {
        int i = idx - N_ENCW - N_ENCI - N_DECW;
        int kt = i / 672, r = i % 672; mt = r / 32; l = r % 32;
        c0 = kt*16 + (l & 3)*2; src = attW; ldk = AK; dst = &g_attfrag[i];
    }
    int mlo = mt*16 + (l >> 2), mhi = mlo + 8;
    uint4 o;
    o.x = pk2(src[mlo*ldk + c0],     src[mlo*ldk + c0 + 1]);
    o.y = pk2(src[mhi*ldk + c0],     src[mhi*ldk + c0 + 1]);
    o.z = pk2(src[mlo*ldk + c0 + 8], src[mlo*ldk + c0 + 9]);
    o.w = pk2(src[mhi*ldk + c0 + 8], src[mhi*ldk + c0 + 9]);
    *dst = o;
}

// ---------------- mma / cluster helpers ----------------
#define MMA(d, a, bb0, bb1) \
    asm volatile("mma.sync.aligned.m16n8k16.row.col.f32.f16.f16.f32 " \
        "{%0,%1,%2,%3}, {%4,%5,%6,%7}, {%8,%9}, {%0,%1,%2,%3};" \
        : "+f"(d[0]), "+f"(d[1]), "+f"(d[2]), "+f"(d[3]) \
        : "r"((a).x), "r"((a).y), "r"((a).z), "r"((a).w), "r"(bb0), "r"(bb1))

#define BFRAG(bb0, bb1, tb, RS, kbase) { \
    const __half* tp_ = (tb) + (l >> 2)*(RS) + (kbase) + (l & 3)*2; \
    bb0 = *(const unsigned int*)tp_; \
    bb1 = *(const unsigned int*)(tp_ + 8); }

__device__ __forceinline__ unsigned int smem_u32(const void* p) {
    unsigned int a;
    asm("{ .reg .u64 t; cvta.to.shared.u64 t, %1; cvt.u32.u64 %0, t; }" : "=r"(a) : "l"(p));
    return a;
}
__device__ __forceinline__ unsigned int mapa32(unsigned int a, unsigned int r) {
    unsigned int o; asm("mapa.shared::cluster.u32 %0, %1, %2;" : "=r"(o) : "r"(a), "r"(r)); return o;
}
__device__ __forceinline__ void stc16(unsigned int a, unsigned short v) {
    asm volatile("st.shared::cluster.u16 [%0], %1;" :: "r"(a), "h"(v));
}
__device__ __forceinline__ void stc32(unsigned int a, unsigned int v) {
    asm volatile("st.shared::cluster.u32 [%0], %1;" :: "r"(a), "r"(v));
}
#define CLUSTER_SYNC() do { \
    asm volatile("barrier.cluster.arrive.aligned;" ::: "memory"); \
    asm volatile("barrier.cluster.wait.aligned;"   ::: "memory"); } while (0)

// ---- encoder step sync: st.async data-carrying exchange + mbarrier ----
__device__ __forceinline__ void mbar_init(unsigned int a, unsigned int cnt) {
    asm volatile("mbarrier.init.shared.b64 [%0], %1;" :: "r"(a), "r"(cnt) : "memory");
}
__device__ __forceinline__ void mbar_expect(unsigned int a, unsigned int bytes) {
    asm volatile("mbarrier.arrive.expect_tx.shared.b64 _, [%0], %1;" :: "r"(a), "r"(bytes) : "memory");
}
__device__ __forceinline__ void stasync32(unsigned int remAddr, unsigned int v, unsigned int remMbar) {
    asm volatile("st.async.shared::cluster.mbarrier::complete_tx::bytes.b32 [%0], %1, [%2];"
                 :: "r"(remAddr), "r"(v), "r"(remMbar) : "memory");
}
__device__ __forceinline__ void mbar_wait(unsigned int a, unsigned int parity) {
    unsigned int done;
    asm volatile("{\n\t.reg .pred p;\n\t"
        "mbarrier.try_wait.parity.acquire.cluster.shared::cta.b64 p, [%1], %2;\n\t"
        "selp.b32 %0, 1, 0, p;\n\t}"
        : "=r"(done) : "r"(a), "r"(parity) : "memory");
    while (!done) {
        asm volatile("{\n\t.reg .pred p;\n\t"
            "mbarrier.try_wait.parity.acquire.cluster.shared::cta.b64 p, [%1], %2;\n\t"
            "selp.b32 %0, 1, 0, p;\n\t}"
            : "=r"(done) : "r"(a), "r"(parity) : "memory");
    }
}

// smem layout (bytes)
#define WC_SLOTS 14
#define OFF_WC 0                          // 14*24*32*16 = 172032
#define OFF_PL 172032                     // planes (stride-10) / scores / scratch: 20480
#define OFF_HF 192512                     // f32 own-j hold [128][10]: 5120
#define OFF_HT 197632                     // fp16 h tables, 2 bufs x 8x312: 9984
#define OFF_CT 207616                     // fp16 comb [8][280]: 4480
#define OFF_BI 212096                     // f32 own-j biases [4][128]: 2048
#define OFF_AB 214144                     // f32 attb [336]: 1344
#define OFF_MB 215552                     // 2 mbarriers: 16
#define SMEM_BYTES 215568
#define HT_RS 312
#define CT_RS 280

__global__ __launch_bounds__(512, 1) __cluster_dims__(2, 1, 1)
void k_all(
    const float* __restrict__ xb,
    const float* __restrict__ ebih, const float* __restrict__ ebhh,
    const float* __restrict__ attb,
    const float* __restrict__ dbih, const float* __restrict__ dbhh,
    const float* __restrict__ outW, const float* __restrict__ outb,
    const float* __restrict__ linW, const float* __restrict__ linb,
    float* __restrict__ dout)
{
    extern __shared__ char smx[];
    uint4*  wc   = (uint4*)(smx + OFF_WC);
    float*  PL   = (float*)(smx + OFF_PL);
    float*  SCR  = (float*)(smx + OFF_PL + 12288);
    float*  hF   = (float*)(smx + OFF_HF);
    __half* hTb0 = (__half*)(smx + OFF_HT);
    __half* hTb1 = (__half*)(smx + OFF_HT + 4992);
    __half* cT   = (__half*)(smx + OFF_CT);
    float*  BI   = (float*)(smx + OFF_BI);
    float*  AB   = (float*)(smx + OFF_AB);

    int tx = threadIdx.x, l = tx & 31, w = tx >> 5;
    unsigned int rank; asm("mov.u32 %0, %%cluster_ctarank;" : "=r"(rank));
    int b0 = (blockIdx.x >> 1) * 8;
    int jbase = (int)rank << 7;
    bool hv = (w < 8);
    int m1 = w, m2 = 16 + w;
    int mtg1 = (m1 >> 3)*16 + (int)rank*8 + (m1 & 7);
    int mtg2 = 32 + (int)rank*8 + (m2 & 7);

    unsigned int peerHT0 = mapa32(smem_u32(hTb0), rank ^ 1u);
    unsigned int peerHT1 = mapa32(smem_u32(hTb1), rank ^ 1u);
    unsigned int peerCT  = mapa32(smem_u32(cT),  rank ^ 1u);
    unsigned int mbL = smem_u32(smx + OFF_MB);
    unsigned int mbP = mapa32(mbL, rank ^ 1u);

    // ---- init: encoder weight cache (kt 0..12 + x slot 13), biases, state ----
    for (int e = tx; e < WC_SLOTS*768; e += 512) {
        int slot = e / 768, m = (e % 768) >> 5, ll = e & 31;
        int mtg = (m >> 3)*16 + (int)rank*8 + (m & 7);
        if (slot < 13)       wc[e] = g_encWfrag[(slot*48 + mtg)*32 + ll];
        else if (slot == 13) wc[e] = g_encIfrag[mtg*32 + ll];
    }
    if (tx == 0) { mbar_init(mbL, 1); mbar_init(mbL + 8, 1); }
    if (tx < 128) {
        BI[tx]       = ebih[jbase + tx]        + ebhh[jbase + tx];
        BI[128 + tx] = ebih[HH + jbase + tx]   + ebhh[HH + jbase + tx];
        BI[256 + tx] = ebih[2*HH + jbase + tx];
        BI[384 + tx] = ebhh[2*HH + jbase + tx];
    }
    for (int e = tx; e < 1280; e += 512) hF[e] = 0.f;
    for (int e = tx; e < 8*HT_RS; e += 512) hTb0[e] = __float2half(0.f);
    __syncthreads();
    if (tx < 128) { int b = tx >> 4, f = tx & 15;
        hTb0[b*HT_RS + 256 + f] = __float2half(xb[((b0 + b)*SS + 0)*FF + f]); }
    CLUSTER_SYNC();

    // ================= ENCODER =================
    for (int s = 0; s < SS; ++s) {
        const __half* hTc = (s & 1) ? hTb1 : hTb0;
        __half*       hTn = (s & 1) ? hTb0 : hTb1;
        unsigned int peerN = (s & 1) ? peerHT0 : peerHT1;
        unsigned int mbuf = (unsigned)(s & 1) << 3;

        float accA0[4] = {}, accA1[4] = {}, accB0[4] = {}, accB1[4] = {};
        unsigned int bb0, bb1;
        uint4 s1a[3], s2a[3];
        #pragma unroll
        for (int i2 = 0; i2 < 3; ++i2) {
            s1a[i2] = g_encWfrag[((13 + i2)*48 + mtg1)*32 + l];
            if (hv) s2a[i2] = g_encWfrag[((13 + i2)*48 + mtg2)*32 + l];
        }
        #pragma unroll
        for (int kt = 0; kt < 13; ++kt) {
            BFRAG(bb0, bb1, hTc, HT_RS, kt*16);
            uint4 a = wc[(kt*24 + m1)*32 + l];
            MMA(accA0, a, bb0, bb1);
            if (hv) { uint4 a2 = wc[(kt*24 + m2)*32 + l]; MMA(accA1, a2, bb0, bb1); }
        }
        #pragma unroll
        for (int i2 = 0; i2 < 3; ++i2) {
            BFRAG(bb0, bb1, hTc, HT_RS, (13 + i2)*16);
            MMA(accA0, s1a[i2], bb0, bb1);
            if (hv) MMA(accA1, s2a[i2], bb0, bb1);
        }
        {   // x tile (k 256..271 of h-table)
            BFRAG(bb0, bb1, hTc, HT_RS, 256);
            uint4 a = wc[(13*24 + m1)*32 + l];  MMA(accB0, a, bb0, bb1);
            if (hv) { uint4 a2 = wc[(13*24 + m2)*32 + l]; MMA(accB1, a2, bb0, bb1); }
        }
        {   // epilogue to gate planes (stride 10)
            int jr = (m1 & 7)*16 + (l >> 2), cb = (l & 3)*2;
            int g = m1 >> 3;
            *(float2*)&PL[(g*128 + jr)*10 + cb]     = make_float2(accA0[0]+accB0[0], accA0[1]+accB0[1]);
            *(float2*)&PL[(g*128 + jr + 8)*10 + cb] = make_float2(accA0[2]+accB0[2], accA0[3]+accB0[3]);
            if (hv) {
                int jr2 = (m2 & 7)*16 + (l >> 2);
                *(float2*)&PL[(256 + jr2)*10 + cb]     = make_float2(accA1[0], accA1[1]);
                *(float2*)&PL[(256 + jr2 + 8)*10 + cb] = make_float2(accA1[2], accA1[3]);
                *(float2*)&PL[(384 + jr2)*10 + cb]     = make_float2(accB1[0], accB1[1]);
                *(float2*)&PL[(384 + jr2 + 8)*10 + cb] = make_float2(accB1[2], accB1[3]);
            }
        }
        __syncthreads();
        {   // GRU update: thread -> (row b, j-pair); st.async pushes carry the sync
            if (tx == 0) mbar_expect(mbL + mbuf, 2048);
            int b = tx >> 6, jp = tx & 63;
            int jl0 = jp*2;
            float h2v[2];
            #pragma unroll
            for (int jj = 0; jj < 2; ++jj) {
                int jl = jl0 + jj;
                float r = sigf(PL[jl*10 + b] + BI[jl]);
                float z = sigf(PL[(128 + jl)*10 + b] + BI[128 + jl]);
                float n = tanhfast(PL[(384 + jl)*10 + b] + BI[256 + jl]
                              + r*(PL[(256 + jl)*10 + b] + BI[384 + jl]));
                float hold = hF[jl*10 + b];
                h2v[jj] = (1.f - z)*n + z*hold;
                hF[jl*10 + b] = h2v[jj];
            }
            __half2 hp = __floats2half2_rn(h2v[0], h2v[1]);
            int j0 = jbase + jl0;
            *(__half2*)&hTn[b*HT_RS + j0] = hp;
            stasync32(peerN + (unsigned)(b*HT_RS + j0)*2, *(unsigned int*)&hp, mbP + mbuf);
            *(__half2*)&g_eoutH[((size_t)(b0 + b)*SS + s)*HH + j0] = hp;
            if (tx < 128 && s + 1 < SS) { int bb = tx >> 4, f = tx & 15;
                hTn[bb*HT_RS + 256 + f] = __float2half(xb[((b0 + bb)*SS + s + 1)*FF + f]); }
        }
        __syncthreads();
        mbar_wait(mbL + mbuf, (unsigned)((s >> 1) & 1));
    }

    // ================= DECODER setup =================
    for (int e = tx; e < WC_SLOTS*768; e += 512) {
        int slot = e / 768, m = (e % 768) >> 5, ll = e & 31;
        int mtg = (m >> 3)*16 + (int)rank*8 + (m & 7);
        wc[e] = g_decWfrag[(slot*48 + mtg)*32 + ll];
    }
    if (tx < 128) {
        BI[tx]       = dbih[jbase + tx]        + dbhh[jbase + tx];
        BI[128 + tx] = dbih[HH + jbase + tx]   + dbhh[HH + jbase + tx];
        BI[256 + tx] = dbih[2*HH + jbase + tx];
        BI[384 + tx] = dbhh[2*HH + jbase + tx];
    }
    for (int e = tx; e < SS; e += 512) AB[e] = attb[e];
    if (tx < 128) { int b = tx >> 4, f = tx & 15;
        hTb0[b*HT_RS + 256 + f] = __float2half(xb[((b0 + b)*SS + (SS - 1))*FF + f]); }
    __syncthreads();

    for (int p = 0; p < PP; ++p) {
        const __half* hTc = (p & 1) ? hTb1 : hTb0;
        __half*       hTn = (p & 1) ? hTb0 : hTb1;
        unsigned int peerN = (p & 1) ? peerHT0 : peerHT1;

        // ---- A: attention scores (both ranks compute all 336) ----
        {
            float ac0[4] = {}, ac1[4] = {};
            unsigned int bb0, bb1;
            bool two = (w < 5);
            uint4 p1 = g_attfrag[(0*21 + w)*32 + l], p2 = p1;
            if (two) p2 = g_attfrag[(0*21 + 16 + w)*32 + l];
            #pragma unroll 1
            for (int kt = 0; kt < 17; ++kt) {
                uint4 c1 = p1, c2 = p2;
                if (kt < 16) {
                    p1 = g_attfrag[((kt + 1)*21 + w)*32 + l];
                    if (two) p2 = g_attfrag[((kt + 1)*21 + 16 + w)*32 + l];
                }
                BFRAG(bb0, bb1, hTc, HT_RS, kt*16);
                MMA(ac0, c1, bb0, bb1);
                if (two) MMA(ac1, c2, bb0, bb1);
            }
            int cb = (l & 3)*2, ro = l >> 2;
            int sr = w*16 + ro;
            *(float2*)&PL[sr*8 + cb]       = make_float2(ac0[0] + AB[sr],     ac0[1] + AB[sr]);
            *(float2*)&PL[(sr + 8)*8 + cb] = make_float2(ac0[2] + AB[sr + 8], ac0[3] + AB[sr + 8]);
            if (two) {
                int sr2 = (16 + w)*16 + ro;
                *(float2*)&PL[sr2*8 + cb]       = make_float2(ac1[0] + AB[sr2],     ac1[1] + AB[sr2]);
                *(float2*)&PL[(sr2 + 8)*8 + cb] = make_float2(ac1[2] + AB[sr2 + 8], ac1[3] + AB[sr2 + 8]);
            }
        }
        __syncthreads();
        // ---- B: softmax (warp = batch row) ----
        if (w < 8) {
            float mx = -1e30f;
            for (int i = l; i < SS; i += 32) mx = fmaxf(mx, PL[i*8 + w]);
            #pragma unroll
            for (int o = 16; o; o >>= 1) mx = fmaxf(mx, __shfl_xor_sync(0xffffffffu, mx, o));
            float sum = 0.f;
            for (int i = l; i < SS; i += 32) {
                float e = __expf(PL[i*8 + w] - mx);
                PL[i*8 + w] = e; sum += e;
            }
            #pragma unroll
            for (int o = 16; o; o >>= 1) sum += __shfl_xor_sync(0xffffffffu, sum, o);
            float inv = 1.f / sum;
            for (int i = l; i < SS; i += 32) PL[i*8 + w] *= inv;
        }
        __syncthreads();
        // ---- C: combine own 128 h-cols; write cT to both ranks ----
        {
            int b = tx >> 6, t = tx & 63, shalf = t >> 5, cq = t & 31;
            const uint2* ep = (const uint2*)(g_eoutH + (size_t)(b0 + b)*SS*HH) + (int)rank*32 + cq;
            float c0 = 0, c1 = 0, c2 = 0, c3 = 0;
            int s0 = shalf*168;
            #pragma unroll 8
            for (int s2 = s0; s2 < s0 + 168; ++s2) {
                float a = PL[s2*8 + b];
                uint2 u = ep[(size_t)s2*64];
                float2 f01 = __half22float2(*(__half2*)&u.x);
                float2 f23 = __half22float2(*(__half2*)&u.y);
                c0 += a*f01.x; c1 += a*f01.y; c2 += a*f23.x; c3 += a*f23.y;
            }
            if (shalf) *(float4*)&SCR[(b*32 + cq)*4] = make_float4(c0, c1, c2, c3);
            __syncthreads();
            if (!shalf) {
                float4 pv = *(float4*)&SCR[(b*32 + cq)*4];
                c0 += pv.x; c1 += pv.y; c2 += pv.z; c3 += pv.w;
                __half2 lo = __floats2half2_rn(c0, c1), hi = __floats2half2_rn(c2, c3);
                int col = jbase + cq*4;
                *(__half2*)&cT[b*CT_RS + col]     = lo;
                *(__half2*)&cT[b*CT_RS + col + 2] = hi;
                unsigned int ad = peerCT + (unsigned)(b*CT_RS + col)*2;
                stc32(ad,     *(unsigned int*)&lo);
                stc32(ad + 4, *(unsigned int*)&hi);
            }
        }
        CLUSTER_SYNC();
        // ---- D: decoder GRU mma (kt<16: Whh x h; kt>=16: Wih x comb) ----
        {
            float accA0[4] = {}, accA1[4] = {}, accB0[4] = {}, accB1[4] = {};
            unsigned int bb0, bb1;
            #pragma unroll
            for (int kt = 0; kt < 14; ++kt) {
                BFRAG(bb0, bb1, hTc, HT_RS, kt*16);
                uint4 a = wc[(kt*24 + m1)*32 + l];
                MMA(accA0, a, bb0, bb1);
                if (hv) { uint4 a2 = wc[(kt*24 + m2)*32 + l]; MMA(accA1, a2, bb0, bb1); }
            }
            uint4 p1 = g_decWfrag[(14*48 + mtg1)*32 + l], p2 = p1;
            if (hv) p2 = g_decWfrag[(14*48 + mtg2)*32 + l];
            #pragma unroll 1
            for (int kt = 14; kt < 32; ++kt) {
                uint4 c1 = p1, c2 = p2;
                if (kt < 31) {
                    p1 = g_decWfrag[((kt + 1)*48 + mtg1)*32 + l];
                    if (hv) p2 = g_decWfrag[((kt + 1)*48 + mtg2)*32 + l];
                }
                if (kt < 16) {
                    BFRAG(bb0, bb1, hTc, HT_RS, kt*16);
                    MMA(accA0, c1, bb0, bb1);
                    if (hv) MMA(accA1, c2, bb0, bb1);
                } else {
                    BFRAG(bb0, bb1, cT, CT_RS, (kt - 16)*16);
                    MMA(accB0, c1, bb0, bb1);
                    if (hv) MMA(accB1, c2, bb0, bb1);
                }
            }
            int jr = (m1 & 7)*16 + (l >> 2), cb = (l & 3)*2;
            int g = m1 >> 3;
            *(float2*)&PL[(g*128 + jr)*10 + cb]     = make_float2(accA0[0]+accB0[0], accA0[1]+accB0[1]);
            *(float2*)&PL[(g*128 + jr + 8)*10 + cb] = make_float2(accA0[2]+accB0[2], accA0[3]+accB0[3]);
            if (hv) {
                int jr2 = (m2 & 7)*16 + (l >> 2);
                *(float2*)&PL[(256 + jr2)*10 + cb]     = make_float2(accA1[0], accA1[1]);
                *(float2*)&PL[(256 + jr2 + 8)*10 + cb] = make_float2(accA1[2], accA1[3]);
                *(float2*)&PL[(384 + jr2)*10 + cb]     = make_float2(accB1[0], accB1[1]);
                *(float2*)&PL[(384 + jr2 + 8)*10 + cb] = make_float2(accB1[2], accB1[3]);
            }
        }
        __syncthreads();
        {   // GRU update own j's; push h2 to both h-tables
            int jl = tx & 127, j = jbase + jl, pr = tx >> 7;
            #pragma unroll
            for (int q = 0; q < 2; ++q) {
                int b = pr*2 + q;
                float r = sigf(PL[jl*10 + b] + BI[jl]);
                float z = sigf(PL[(128 + jl)*10 + b] + BI[128 + jl]);
                float n = tanhfast(PL[(384 + jl)*10 + b] + BI[256 + jl]
                              + r*(PL[(256 + jl)*10 + b] + BI[384 + jl]));
                float hold = hF[jl*10 + b];
                float h2 = (1.f - z)*n + z*hold;
                hF[jl*10 + b] = h2;
                __half hh = __float2half(h2);
                hTn[b*HT_RS + j] = hh;
                stc16(peerN + (unsigned)(b*HT_RS + j)*2, *(unsigned short*)&hh);
            }
        }
        CLUSTER_SYNC();
        // ---- E: out projection + final linear (both ranks; rank0 writes dout) ----
        if (w < 8) {
            float fin = 0.f;
            #pragma unroll
            for (int f = 0; f < FF; ++f) {
                float acc = 0.f;
                #pragma unroll
                for (int k = l; k < HH; k += 32)
                    acc += __half2float(hTn[w*HT_RS + k]) * outW[f*HH + k];
                #pragma unroll
                for (int o = 16; o; o >>= 1) acc += __shfl_xor_sync(0xffffffffu, acc, o);
                if (l == 0) {
                    float ov = acc + outb[f];
                    hTn[w*HT_RS + 256 + f] = __float2half(ov);
                    fin += ov * linW[f];
                }
            }
            if (l == 0 && rank == 0) dout[(b0 + w)*PP + p] = fin + linb[0];
        }
        __syncthreads();
    }
}

// ---------------- launch ----------------
extern "C" void kernel_launch(void* const* d_in, const int* in_sizes, int n_in,
                              void* d_out, int out_size)
{
    const float* xb   = (const float*)d_in[0];
    const float* eWih = (const float*)d_in[1];
    const float* eWhh = (const float*)d_in[2];
    const float* ebih = (const float*)d_in[3];
    const float* ebhh = (const float*)d_in[4];
    const float* attW = (const float*)d_in[5];
    const float* attb = (const float*)d_in[6];
    const float* dWih = (const float*)d_in[7];
    const float* dWhh = (const float*)d_in[8];
    const float* dbih = (const float*)d_in[9];
    const float* dbhh = (const float*)d_in[10];
    const float* outW = (const float*)d_in[11];
    const float* outb = (const float*)d_in[12];
    const float* linW = (const float*)d_in[13];
    const float* linb = (const float*)d_in[14];
    float* dout = (float*)d_out;

    cudaFuncSetAttribute(k_all, cudaFuncAttributeMaxDynamicSharedMemorySize, SMEM_BYTES);

    k_prep<<<(PREP_N + 255) / 256, 256>>>(eWih, eWhh, dWih, dWhh, attW);
    k_all<<<BB / 4, 512, SMEM_BYTES>>>(xb, ebih, ebhh, attb, dbih, dbhh,
                                       outW, outb, linW, linb, dout);
}

// round 17
// speedup vs baseline: 1.3536x; 1.0226x over previous
#include <cuda_runtime.h>
#include <cuda_fp16.h>
#include <math.h>

#define BB 512
#define SS 336
#define FF 16
#define HH 256
#define PP 48
#define AK 272   // HH+FF

// ---------------- fragment-major prepared weights (device globals) ----------------
__device__ uint4 g_encWfrag[16*48*32];   // enc Whh  (393 KB)
__device__ uint4 g_encIfrag[   48*32];   // enc Wih  (24 KB, single ktile K=16)
__device__ uint4 g_decWfrag[32*48*32];   // dec [Whh | Wih] kt<16 / kt>=16 (786 KB)
__device__ uint4 g_attfrag [17*21*32];   // att_W 336x272 (183 KB)
__device__ __half g_eoutH[(size_t)BB*SS*HH]; // encoder outputs fp16 (88 MB)

__device__ __forceinline__ float sigf(float x) { return 1.f / (1.f + __expf(-x)); }
// fast tanh: tanh(x) = 1 - 2/(e^{2x}+1); safe at both extremes
__device__ __forceinline__ float tanhfast(float x) {
    return 1.f - 2.f / (__expf(2.f * x) + 1.f);
}
__device__ __forceinline__ unsigned int pk2(float a, float b) {
    __half2 h = __floats2half2_rn(a, b);
    return *reinterpret_cast<unsigned int*>(&h);
}

// ---------------- prep: build all fragments ----------------
#define N_ENCW (16*48*32)
#define N_ENCI (48*32)
#define N_DECW (32*48*32)
#define N_ATT  (17*21*32)
#define PREP_N (N_ENCW + N_ENCI + N_DECW + N_ATT)

__global__ void k_prep(const float* __restrict__ eWih, const float* __restrict__ eWhh,
                       const float* __restrict__ dWih, const float* __restrict__ dWhh,
                       const float* __restrict__ attW)
{
    int idx = blockIdx.x * 256 + threadIdx.x;
    if (idx >= PREP_N) return;
    const float* src; uint4* dst; int mt, l, c0, ldk;
    if (idx < N_ENCW) {
        int kt = idx / 1536, r = idx % 1536; mt = r / 32; l = r % 32;
        c0 = kt*16 + (l & 3)*2; src = eWhh; ldk = HH; dst = &g_encWfrag[idx];
    } else if (idx < N_ENCW + N_ENCI) {
        int i = idx - N_ENCW; mt = i / 32; l = i % 32;
        c0 = (l & 3)*2; src = eWih; ldk = FF; dst = &g_encIfrag[i];
    } else if (idx < N_ENCW + N_ENCI + N_DECW) {
        int i = idx - N_ENCW - N_ENCI;
        int kt = i / 1536, r = i % 1536; mt = r / 32; l = r % 32;
        if (kt < 16) { src = dWhh; c0 = kt*16 + (l & 3)*2; }
        else         { src = dWih; c0 = (kt - 16)*16 + (l & 3)*2; }
        ldk = HH; dst = &g_decWfrag[i];
    } else {
        int i = idx - N_ENCW - N_ENCI - N_DECW;
        int kt = i / 672, r = i % 672; mt = r / 32; l = r % 32;
        c0 = kt*16 + (l & 3)*2; src = attW; ldk = AK; dst = &g_attfrag[i];
    }
    int mlo = mt*16 + (l >> 2), mhi = mlo + 8;
    uint4 o;
    o.x = pk2(src[mlo*ldk + c0],     src[mlo*ldk + c0 + 1]);
    o.y = pk2(src[mhi*ldk + c0],     src[mhi*ldk + c0 + 1]);
    o.z = pk2(src[mlo*ldk + c0 + 8], src[mlo*ldk + c0 + 9]);
    o.w = pk2(src[mhi*ldk + c0 + 8], src[mhi*ldk + c0 + 9]);
    *dst = o;
}

// ---------------- mma / cluster helpers ----------------
#define MMA(d, a, bb0, bb1) \
    asm volatile("mma.sync.aligned.m16n8k16.row.col.f32.f16.f16.f32 " \
        "{%0,%1,%2,%3}, {%4,%5,%6,%7}, {%8,%9}, {%0,%1,%2,%3};" \
        : "+f"(d[0]), "+f"(d[1]), "+f"(d[2]), "+f"(d[3]) \
        : "r"((a).x), "r"((a).y), "r"((a).z), "r"((a).w), "r"(bb0), "r"(bb1))

#define BFRAG(bb0, bb1, tb, RS, kbase) { \
    const __half* tp_ = (tb) + (l >> 2)*(RS) + (kbase) + (l & 3)*2; \
    bb0 = *(const unsigned int*)tp_; \
    bb1 = *(const unsigned int*)(tp_ + 8); }

__device__ __forceinline__ unsigned int smem_u32(const void* p) {
    unsigned int a;
    asm("{ .reg .u64 t; cvta.to.shared.u64 t, %1; cvt.u32.u64 %0, t; }" : "=r"(a) : "l"(p));
    return a;
}
__device__ __forceinline__ unsigned int mapa32(unsigned int a, unsigned int r) {
    unsigned int o; asm("mapa.shared::cluster.u32 %0, %1, %2;" : "=r"(o) : "r"(a), "r"(r)); return o;
}
__device__ __forceinline__ void stc32(unsigned int a, unsigned int v) {
    asm volatile("st.shared::cluster.u32 [%0], %1;" :: "r"(a), "r"(v));
}
#define CLUSTER_SYNC() do { \
    asm volatile("barrier.cluster.arrive.aligned;" ::: "memory"); \
    asm volatile("barrier.cluster.wait.aligned;"   ::: "memory"); } while (0)

// ---- st.async data-carrying exchange + mbarrier ----
__device__ __forceinline__ void mbar_init(unsigned int a, unsigned int cnt) {
    asm volatile("mbarrier.init.shared.b64 [%0], %1;" :: "r"(a), "r"(cnt) : "memory");
}
__device__ __forceinline__ void mbar_expect(unsigned int a, unsigned int bytes) {
    asm volatile("mbarrier.arrive.expect_tx.shared.b64 _, [%0], %1;" :: "r"(a), "r"(bytes) : "memory");
}
__device__ __forceinline__ void stasync32(unsigned int remAddr, unsigned int v, unsigned int remMbar) {
    asm volatile("st.async.shared::cluster.mbarrier::complete_tx::bytes.b32 [%0], %1, [%2];"
                 :: "r"(remAddr), "r"(v), "r"(remMbar) : "memory");
}
__device__ __forceinline__ void mbar_wait(unsigned int a, unsigned int parity) {
    unsigned int done;
    asm volatile("{\n\t.reg .pred p;\n\t"
        "mbarrier.try_wait.parity.acquire.cluster.shared::cta.b64 p, [%1], %2;\n\t"
        "selp.b32 %0, 1, 0, p;\n\t}"
        : "=r"(done) : "r"(a), "r"(parity) : "memory");
    while (!done) {
        asm volatile("{\n\t.reg .pred p;\n\t"
            "mbarrier.try_wait.parity.acquire.cluster.shared::cta.b64 p, [%1], %2;\n\t"
            "selp.b32 %0, 1, 0, p;\n\t}"
            : "=r"(done) : "r"(a), "r"(parity) : "memory");
    }
}

// smem layout (bytes)
#define WC_SLOTS 14
#define OFF_WC 0                          // 14*24*32*16 = 172032
#define OFF_PL 172032                     // planes (stride-10) / scores / scratch: 20480
#define OFF_HF 192512                     // f32 own-j hold [128][10]: 5120
#define OFF_HT 197632                     // fp16 h tables, 2 bufs x 8x312: 9984
#define OFF_CT 207616                     // fp16 comb [8][280]: 4480
#define OFF_BI 212096                     // f32 own-j biases [4][128]: 2048
#define OFF_AB 214144                     // f32 attb [336]: 1344
#define OFF_MB 215552                     // 6 mbarriers: enc h x2 | dec h x2 | dec cT x2
#define SMEM_BYTES 215600
#define HT_RS 312
#define CT_RS 280

__global__ __launch_bounds__(512, 1) __cluster_dims__(2, 1, 1)
void k_all(
    const float* __restrict__ xb,
    const float* __restrict__ ebih, const float* __restrict__ ebhh,
    const float* __restrict__ attb,
    const float* __restrict__ dbih, const float* __restrict__ dbhh,
    const float* __restrict__ outW, const float* __restrict__ outb,
    const float* __restrict__ linW, const float* __restrict__ linb,
    float* __restrict__ dout)
{
    extern __shared__ char smx[];
    uint4*  wc   = (uint4*)(smx + OFF_WC);
    float*  PL   = (float*)(smx + OFF_PL);
    float*  SCR  = (float*)(smx + OFF_PL + 12288);
    float*  hF   = (float*)(smx + OFF_HF);
    __half* hTb0 = (__half*)(smx + OFF_HT);
    __half* hTb1 = (__half*)(smx + OFF_HT + 4992);
    __half* cT   = (__half*)(smx + OFF_CT);
    float*  BI   = (float*)(smx + OFF_BI);
    float*  AB   = (float*)(smx + OFF_AB);

    int tx = threadIdx.x, l = tx & 31, w = tx >> 5;
    unsigned int rank; asm("mov.u32 %0, %%cluster_ctarank;" : "=r"(rank));
    int b0 = (blockIdx.x >> 1) * 8;
    int jbase = (int)rank << 7;
    bool hv = (w < 8);
    int m1 = w, m2 = 16 + w;
    int mtg1 = (m1 >> 3)*16 + (int)rank*8 + (m1 & 7);
    int mtg2 = 32 + (int)rank*8 + (m2 & 7);

    unsigned int peerHT0 = mapa32(smem_u32(hTb0), rank ^ 1u);
    unsigned int peerHT1 = mapa32(smem_u32(hTb1), rank ^ 1u);
    unsigned int peerCT  = mapa32(smem_u32(cT),  rank ^ 1u);
    unsigned int mbL = smem_u32(smx + OFF_MB);
    unsigned int mbP = mapa32(mbL, rank ^ 1u);

    // ---- init: encoder weight cache (kt 0..12 + x slot 13), biases, state ----
    for (int e = tx; e < WC_SLOTS*768; e += 512) {
        int slot = e / 768, m = (e % 768) >> 5, ll = e & 31;
        int mtg = (m >> 3)*16 + (int)rank*8 + (m & 7);
        if (slot < 13)       wc[e] = g_encWfrag[(slot*48 + mtg)*32 + ll];
        else if (slot == 13) wc[e] = g_encIfrag[mtg*32 + ll];
    }
    if (tx == 0) {
        mbar_init(mbL, 1);      mbar_init(mbL + 8, 1);    // encoder h
        mbar_init(mbL + 16, 1); mbar_init(mbL + 24, 1);   // decoder h
        mbar_init(mbL + 32, 1); mbar_init(mbL + 40, 1);   // decoder cT
    }
    if (tx < 128) {
        BI[tx]       = ebih[jbase + tx]        + ebhh[jbase + tx];
        BI[128 + tx] = ebih[HH + jbase + tx]   + ebhh[HH + jbase + tx];
        BI[256 + tx] = ebih[2*HH + jbase + tx];
        BI[384 + tx] = ebhh[2*HH + jbase + tx];
    }
    for (int e = tx; e < 1280; e += 512) hF[e] = 0.f;
    for (int e = tx; e < 8*HT_RS; e += 512) hTb0[e] = __float2half(0.f);
    __syncthreads();
    if (tx < 128) { int b = tx >> 4, f = tx & 15;
        hTb0[b*HT_RS + 256 + f] = __float2half(xb[((b0 + b)*SS + 0)*FF + f]); }
    CLUSTER_SYNC();

    // ================= ENCODER =================
    for (int s = 0; s < SS; ++s) {
        const __half* hTc = (s & 1) ? hTb1 : hTb0;
        __half*       hTn = (s & 1) ? hTb0 : hTb1;
        unsigned int peerN = (s & 1) ? peerHT0 : peerHT1;
        unsigned int mbuf = (unsigned)(s & 1) << 3;

        float accA0[4] = {}, accA1[4] = {}, accB0[4] = {}, accB1[4] = {};
        unsigned int bb0, bb1;
        uint4 s1a[3], s2a[3];
        #pragma unroll
        for (int i2 = 0; i2 < 3; ++i2) {
            s1a[i2] = g_encWfrag[((13 + i2)*48 + mtg1)*32 + l];
            if (hv) s2a[i2] = g_encWfrag[((13 + i2)*48 + mtg2)*32 + l];
        }
        #pragma unroll
        for (int kt = 0; kt < 13; ++kt) {
            BFRAG(bb0, bb1, hTc, HT_RS, kt*16);
            uint4 a = wc[(kt*24 + m1)*32 + l];
            MMA(accA0, a, bb0, bb1);
            if (hv) { uint4 a2 = wc[(kt*24 + m2)*32 + l]; MMA(accA1, a2, bb0, bb1); }
        }
        #pragma unroll
        for (int i2 = 0; i2 < 3; ++i2) {
            BFRAG(bb0, bb1, hTc, HT_RS, (13 + i2)*16);
            MMA(accA0, s1a[i2], bb0, bb1);
            if (hv) MMA(accA1, s2a[i2], bb0, bb1);
        }
        {   // x tile (k 256..271 of h-table)
            BFRAG(bb0, bb1, hTc, HT_RS, 256);
            uint4 a = wc[(13*24 + m1)*32 + l];  MMA(accB0, a, bb0, bb1);
            if (hv) { uint4 a2 = wc[(13*24 + m2)*32 + l]; MMA(accB1, a2, bb0, bb1); }
        }
        {   // epilogue to gate planes (stride 10)
            int jr = (m1 & 7)*16 + (l >> 2), cb = (l & 3)*2;
            int g = m1 >> 3;
            *(float2*)&PL[(g*128 + jr)*10 + cb]     = make_float2(accA0[0]+accB0[0], accA0[1]+accB0[1]);
            *(float2*)&PL[(g*128 + jr + 8)*10 + cb] = make_float2(accA0[2]+accB0[2], accA0[3]+accB0[3]);
            if (hv) {
                int jr2 = (m2 & 7)*16 + (l >> 2);
                *(float2*)&PL[(256 + jr2)*10 + cb]     = make_float2(accA1[0], accA1[1]);
                *(float2*)&PL[(256 + jr2 + 8)*10 + cb] = make_float2(accA1[2], accA1[3]);
                *(float2*)&PL[(384 + jr2)*10 + cb]     = make_float2(accB1[0], accB1[1]);
                *(float2*)&PL[(384 + jr2 + 8)*10 + cb] = make_float2(accB1[2], accB1[3]);
            }
        }
        __syncthreads();
        {   // GRU update: thread -> (row b, j-pair); st.async pushes carry the sync
            if (tx == 0) mbar_expect(mbL + mbuf, 2048);
            int b = tx >> 6, jp = tx & 63;
            int jl0 = jp*2;
            float h2v[2];
            #pragma unroll
            for (int jj = 0; jj < 2; ++jj) {
                int jl = jl0 + jj;
                float r = sigf(PL[jl*10 + b] + BI[jl]);
                float z = sigf(PL[(128 + jl)*10 + b] + BI[128 + jl]);
                float n = tanhfast(PL[(384 + jl)*10 + b] + BI[256 + jl]
                              + r*(PL[(256 + jl)*10 + b] + BI[384 + jl]));
                float hold = hF[jl*10 + b];
                h2v[jj] = (1.f - z)*n + z*hold;
                hF[jl*10 + b] = h2v[jj];
            }
            __half2 hp = __floats2half2_rn(h2v[0], h2v[1]);
            int j0 = jbase + jl0;
            *(__half2*)&hTn[b*HT_RS + j0] = hp;
            stasync32(peerN + (unsigned)(b*HT_RS + j0)*2, *(unsigned int*)&hp, mbP + mbuf);
            *(__half2*)&g_eoutH[((size_t)(b0 + b)*SS + s)*HH + j0] = hp;
            if (tx < 128 && s + 1 < SS) { int bb = tx >> 4, f = tx & 15;
                hTn[bb*HT_RS + 256 + f] = __float2half(xb[((b0 + bb)*SS + s + 1)*FF + f]); }
        }
        __syncthreads();
        mbar_wait(mbL + mbuf, (unsigned)((s >> 1) & 1));
    }

    // ================= DECODER setup =================
    for (int e = tx; e < WC_SLOTS*768; e += 512) {
        int slot = e / 768, m = (e % 768) >> 5, ll = e & 31;
        int mtg = (m >> 3)*16 + (int)rank*8 + (m & 7);
        wc[e] = g_decWfrag[(slot*48 + mtg)*32 + ll];
    }
    if (tx < 128) {
        BI[tx]       = dbih[jbase + tx]        + dbhh[jbase + tx];
        BI[128 + tx] = dbih[HH + jbase + tx]   + dbhh[HH + jbase + tx];
        BI[256 + tx] = dbih[2*HH + jbase + tx];
        BI[384 + tx] = dbhh[2*HH + jbase + tx];
    }
    for (int e = tx; e < SS; e += 512) AB[e] = attb[e];
    if (tx < 128) { int b = tx >> 4, f = tx & 15;
        hTb0[b*HT_RS + 256 + f] = __float2half(xb[((b0 + b)*SS + (SS - 1))*FF + f]); }
    __syncthreads();

    for (int p = 0; p < PP; ++p) {
        const __half* hTc = (p & 1) ? hTb1 : hTb0;
        __half*       hTn = (p & 1) ? hTb0 : hTb1;
        unsigned int peerN = (p & 1) ? peerHT0 : peerHT1;
        unsigned int hbuf = 16u + ((unsigned)(p & 1) << 3);
        unsigned int cbuf = 32u + ((unsigned)(p & 1) << 3);
        unsigned int par  = (unsigned)((p >> 1) & 1);

        // ---- A: attention scores (both ranks compute all 336) ----
        {
            float ac0[4] = {}, ac1[4] = {};
            unsigned int bb0, bb1;
            bool two = (w < 5);
            uint4 p1 = g_attfrag[(0*21 + w)*32 + l], p2 = p1;
            if (two) p2 = g_attfrag[(0*21 + 16 + w)*32 + l];
            #pragma unroll 1
            for (int kt = 0; kt < 17; ++kt) {
                uint4 c1 = p1, c2 = p2;
                if (kt < 16) {
                    p1 = g_attfrag[((kt + 1)*21 + w)*32 + l];
                    if (two) p2 = g_attfrag[((kt + 1)*21 + 16 + w)*32 + l];
                }
                BFRAG(bb0, bb1, hTc, HT_RS, kt*16);
                MMA(ac0, c1, bb0, bb1);
                if (two) MMA(ac1, c2, bb0, bb1);
            }
            int cb = (l & 3)*2, ro = l >> 2;
            int sr = w*16 + ro;
            *(float2*)&PL[sr*8 + cb]       = make_float2(ac0[0] + AB[sr],     ac0[1] + AB[sr]);
            *(float2*)&PL[(sr + 8)*8 + cb] = make_float2(ac0[2] + AB[sr + 8], ac0[3] + AB[sr + 8]);
            if (two) {
                int sr2 = (16 + w)*16 + ro;
                *(float2*)&PL[sr2*8 + cb]       = make_float2(ac1[0] + AB[sr2],     ac1[1] + AB[sr2]);
                *(float2*)&PL[(sr2 + 8)*8 + cb] = make_float2(ac1[2] + AB[sr2 + 8], ac1[3] + AB[sr2 + 8]);
            }
        }
        __syncthreads();
        // ---- B: softmax (warp = batch row) ----
        if (w < 8) {
            float mx = -1e30f;
            for (int i = l; i < SS; i += 32) mx = fmaxf(mx, PL[i*8 + w]);
            #pragma unroll
            for (int o = 16; o; o >>= 1) mx = fmaxf(mx, __shfl_xor_sync(0xffffffffu, mx, o));
            float sum = 0.f;
            for (int i = l; i < SS; i += 32) {
                float e = __expf(PL[i*8 + w] - mx);
                PL[i*8 + w] = e; sum += e;
            }
            #pragma unroll
            for (int o = 16; o; o >>= 1) sum += __shfl_xor_sync(0xffffffffu, sum, o);
            float inv = 1.f / sum;
            for (int i = l; i < SS; i += 32) PL[i*8 + w] *= inv;
        }
        __syncthreads();
        // ---- C: combine own 128 h-cols; st.async pushes to peer cT ----
        {
            if (tx == 0) mbar_expect(mbL + cbuf, 2048);
            int b = tx >> 6, t = tx & 63, shalf = t >> 5, cq = t & 31;
            const uint2* ep = (const uint2*)(g_eoutH + (size_t)(b0 + b)*SS*HH) + (int)rank*32 + cq;
            float c0 = 0, c1 = 0, c2 = 0, c3 = 0;
            int s0 = shalf*168;
            #pragma unroll 8
            for (int s2 = s0; s2 < s0 + 168; ++s2) {
                float a = PL[s2*8 + b];
                uint2 u = ep[(size_t)s2*64];
                float2 f01 = __half22float2(*(__half2*)&u.x);
                float2 f23 = __half22float2(*(__half2*)&u.y);
                c0 += a*f01.x; c1 += a*f01.y; c2 += a*f23.x; c3 += a*f23.y;
            }
            if (shalf) *(float4*)&SCR[(b*32 + cq)*4] = make_float4(c0, c1, c2, c3);
            __syncthreads();
            if (!shalf) {
                float4 pv = *(float4*)&SCR[(b*32 + cq)*4];
                c0 += pv.x; c1 += pv.y; c2 += pv.z; c3 += pv.w;
                __half2 lo = __floats2half2_rn(c0, c1), hi = __floats2half2_rn(c2, c3);
                int col = jbase + cq*4;
                *(__half2*)&cT[b*CT_RS + col]     = lo;
                *(__half2*)&cT[b*CT_RS + col + 2] = hi;
                unsigned int ad = peerCT + (unsigned)(b*CT_RS + col)*2;
                stasync32(ad,     *(unsigned int*)&lo, mbP + cbuf);
                stasync32(ad + 4, *(unsigned int*)&hi, mbP + cbuf);
            }
        }
        __syncthreads();
        mbar_wait(mbL + cbuf, par);
        // ---- D: decoder GRU mma (kt<16: Whh x h; kt>=16: Wih x comb) ----
        {
            float accA0[4] = {}, accA1[4] = {}, accB0[4] = {}, accB1[4] = {};
            unsigned int bb0, bb1;
            #pragma unroll
            for (int kt = 0; kt < 14; ++kt) {
                BFRAG(bb0, bb1, hTc, HT_RS, kt*16);
                uint4 a = wc[(kt*24 + m1)*32 + l];
                MMA(accA0, a, bb0, bb1);
                if (hv) { uint4 a2 = wc[(kt*24 + m2)*32 + l]; MMA(accA1, a2, bb0, bb1); }
            }
            uint4 p1 = g_decWfrag[(14*48 + mtg1)*32 + l], p2 = p1;
            if (hv) p2 = g_decWfrag[(14*48 + mtg2)*32 + l];
            #pragma unroll 1
            for (int kt = 14; kt < 32; ++kt) {
                uint4 c1 = p1, c2 = p2;
                if (kt < 31) {
                    p1 = g_decWfrag[((kt + 1)*48 + mtg1)*32 + l];
                    if (hv) p2 = g_decWfrag[((kt + 1)*48 + mtg2)*32 + l];
                }
                if (kt < 16) {
                    BFRAG(bb0, bb1, hTc, HT_RS, kt*16);
                    MMA(accA0, c1, bb0, bb1);
                    if (hv) MMA(accA1, c2, bb0, bb1);
                } else {
                    BFRAG(bb0, bb1, cT, CT_RS, (kt - 16)*16);
                    MMA(accB0, c1, bb0, bb1);
                    if (hv) MMA(accB1, c2, bb0, bb1);
                }
            }
            int jr = (m1 & 7)*16 + (l >> 2), cb = (l & 3)*2;
            int g = m1 >> 3;
            *(float2*)&PL[(g*128 + jr)*10 + cb]     = make_float2(accA0[0]+accB0[0], accA0[1]+accB0[1]);
            *(float2*)&PL[(g*128 + jr + 8)*10 + cb] = make_float2(accA0[2]+accB0[2], accA0[3]+accB0[3]);
            if (hv) {
                int jr2 = (m2 & 7)*16 + (l >> 2);
                *(float2*)&PL[(256 + jr2)*10 + cb]     = make_float2(accA1[0], accA1[1]);
                *(float2*)&PL[(256 + jr2 + 8)*10 + cb] = make_float2(accA1[2], accA1[3]);
                *(float2*)&PL[(384 + jr2)*10 + cb]     = make_float2(accB1[0], accB1[1]);
                *(float2*)&PL[(384 + jr2 + 8)*10 + cb] = make_float2(accB1[2], accB1[3]);
            }
        }
        __syncthreads();
        {   // GRU update: thread -> (row b, j-pair); st.async pushes to peer h-table
            if (tx == 0) mbar_expect(mbL + hbuf, 2048);
            int b = tx >> 6, jp = tx & 63;
            int jl0 = jp*2;
            float h2v[2];
            #pragma unroll
            for (int jj = 0; jj < 2; ++jj) {
                int jl = jl0 + jj;
                float r = sigf(PL[jl*10 + b] + BI[jl]);
                float z = sigf(PL[(128 + jl)*10 + b] + BI[128 + jl]);
                float n = tanhfast(PL[(384 + jl)*10 + b] + BI[256 + jl]
                              + r*(PL[(256 + jl)*10 + b] + BI[384 + jl]));
                float hold = hF[jl*10 + b];
                h2v[jj] = (1.f - z)*n + z*hold;
                hF[jl*10 + b] = h2v[jj];
            }
            __half2 hp = __floats2half2_rn(h2v[0], h2v[1]);
            int j0 = jbase + jl0;
            *(__half2*)&hTn[b*HT_RS + j0] = hp;
            stasync32(peerN + (unsigned)(b*HT_RS + j0)*2, *(unsigned int*)&hp, mbP + hbuf);
        }
        __syncthreads();
        mbar_wait(mbL + hbuf, par);
        // ---- E: out projection + final linear (both ranks; rank0 writes dout) ----
        if (w < 8) {
            float fin = 0.f;
            #pragma unroll
            for (int f = 0; f < FF; ++f) {
                float acc = 0.f;
                #pragma unroll
                for (int k = l; k < HH; k += 32)
                    acc += __half2float(hTn[w*HT_RS + k]) * outW[f*HH + k];
                #pragma unroll
                for (int o = 16; o; o >>= 1) acc += __shfl_xor_sync(0xffffffffu, acc, o);
                if (l == 0) {
                    float ov = acc + outb[f];
                    hTn[w*HT_RS + 256 + f] = __float2half(ov);
                    fin += ov * linW[f];
                }
            }
            if (l == 0 && rank == 0) dout[(b0 + w)*PP + p] = fin + linb[0];
        }
        __syncthreads();
    }
}

// ---------------- launch ----------------
extern "C" void kernel_launch(void* const* d_in, const int* in_sizes, int n_in,
                              void* d_out, int out_size)
{
    const float* xb   = (const float*)d_in[0];
    const float* eWih = (const float*)d_in[1];
    const float* eWhh = (const float*)d_in[2];
    const float* ebih = (const float*)d_in[3];
    const float* ebhh = (const float*)d_in[4];
    const float* attW = (const float*)d_in[5];
    const float* attb = (const float*)d_in[6];
    const float* dWih = (const float*)d_in[7];
    const float* dWhh = (const float*)d_in[8];
    const float* dbih = (const float*)d_in[9];
    const float* dbhh = (const float*)d_in[10];
    const float* outW = (const float*)d_in[11];
    const float* outb = (const float*)d_in[12];
    const float* linW = (const float*)d_in[13];
    const float* linb = (const float*)d_in[14];
    float* dout = (float*)d_out;

    cudaFuncSetAttribute(k_all, cudaFuncAttributeMaxDynamicSharedMemorySize, SMEM_BYTES);

    k_prep<<<(PREP_N + 255) / 256, 256>>>(eWih, eWhh, dWih, dWhh, attW);
    k_all<<<BB / 4, 512, SMEM_BYTES>>>(xb, ebih, ebhh, attb, dbih, dbhh,
                                       outW, outb, linW, linb, dout);
}